// round 1
// baseline (speedup 1.0000x reference)
#include <cuda_runtime.h>
#include <math.h>

#define S_TOK   4096
#define D_INNER 320
#define HEADS   8
#define DHEAD   40
#define CTX_LEN 77
#define CTX_DIM 768
#define FF_IN   2560   // 2*FF_INNER
#define FF_HALF 1280
#define ATT_SCALE 0.15811388300841897f  // 40^-0.5

// ---------------- scratch (static device globals; no allocs allowed) ----------
__device__ float g_gn  [S_TOK * D_INNER];
__device__ float g_h   [S_TOK * D_INNER];
__device__ float g_hn  [S_TOK * D_INNER];
__device__ float g_q   [S_TOK * D_INNER];
__device__ float g_k   [S_TOK * D_INNER];
__device__ float g_v   [S_TOK * D_INNER];
__device__ float g_attn[S_TOK * D_INNER];
__device__ float g_ff  [S_TOK * FF_IN];
__device__ float g_act [S_TOK * FF_HALF];
__device__ float g_k2  [CTX_LEN * D_INNER];
__device__ float g_v2  [CTX_LEN * D_INNER];

// ---------------- GroupNorm (32 groups of 10 ch x 4096) + transpose to [s,c] --
__global__ void groupnorm_kernel(const float* __restrict__ x,
                                 const float* __restrict__ scale,
                                 const float* __restrict__ bias,
                                 float* __restrict__ outT)
{
    const int g = blockIdx.x;          // 0..31
    const int c0 = g * 10;
    const int N = 10 * S_TOK;          // 40960
    __shared__ float ssum[256], ssq[256];
    float s = 0.f, sq = 0.f;
    for (int i = threadIdx.x; i < N; i += 256) {
        float v = x[c0 * S_TOK + i];
        s += v; sq += v * v;
    }
    ssum[threadIdx.x] = s; ssq[threadIdx.x] = sq;
    __syncthreads();
    for (int off = 128; off > 0; off >>= 1) {
        if (threadIdx.x < off) {
            ssum[threadIdx.x] += ssum[threadIdx.x + off];
            ssq[threadIdx.x]  += ssq[threadIdx.x + off];
        }
        __syncthreads();
    }
    __shared__ float smean, srstd;
    if (threadIdx.x == 0) {
        float mean = ssum[0] / (float)N;
        float var  = ssq[0] / (float)N - mean * mean;
        smean = mean;
        srstd = rsqrtf(var + 1e-6f);
    }
    __syncthreads();
    float mean = smean, rstd = srstd;
    for (int i = threadIdx.x; i < N; i += 256) {
        int c = c0 + i / S_TOK;
        int sp = i - (i / S_TOK) * S_TOK;
        float v = (x[c0 * S_TOK + i] - mean) * rstd * scale[c] + bias[c];
        outT[sp * D_INNER + c] = v;
    }
}

// ---------------- LayerNorm: one warp per row of 320 --------------------------
__global__ void layernorm_kernel(const float* __restrict__ in,
                                 const float* __restrict__ s,
                                 const float* __restrict__ b,
                                 float* __restrict__ out)
{
    int row = blockIdx.x * 8 + (threadIdx.x >> 5);
    int lane = threadIdx.x & 31;
    const float* xr = in + row * D_INNER;
    float sum = 0.f, sq = 0.f;
    for (int i = lane; i < D_INNER; i += 32) {
        float v = xr[i];
        sum += v; sq += v * v;
    }
    #pragma unroll
    for (int off = 16; off > 0; off >>= 1) {
        sum += __shfl_xor_sync(0xffffffffu, sum, off);
        sq  += __shfl_xor_sync(0xffffffffu, sq,  off);
    }
    float mean = sum / (float)D_INNER;
    float var  = sq / (float)D_INNER - mean * mean;
    float rstd = rsqrtf(var + 1e-5f);
    for (int i = lane; i < D_INNER; i += 32)
        out[row * D_INNER + i] = (xr[i] - mean) * rstd * s[i] + b[i];
}

// ---------------- tiled fp32 SGEMM, 64x64x16, 4x4 per thread ------------------
// C = A(MxK) @ B(KxN) [+ bias[n]] [+ resid] ; flags bit0: transposed store
// normal:     C[m*N+n], resid[m*N+n]
// transposed: C[n*M+m], resid[n*M+m]
#define BM 64
#define BN 64
#define BKK 16
__global__ __launch_bounds__(256)
void sgemm_kernel(const float* __restrict__ A, const float* __restrict__ B,
                  const float* __restrict__ bias, const float* __restrict__ resid,
                  float* __restrict__ C, int M, int N, int K, int flags)
{
    __shared__ float As[BKK][BM];
    __shared__ float Bs[BKK][BN];
    const int bm = blockIdx.y * BM;
    const int bn = blockIdx.x * BN;
    const int tid = threadIdx.x;
    const int tx = tid & 15;      // 0..15  -> 4 cols each
    const int ty = tid >> 4;      // 0..15  -> 4 rows each
    const int arow = tid >> 2;            // 0..63
    const int acol = (tid & 3) * 4;       // 0,4,8,12
    const int brow = tid >> 4;            // 0..15
    const int bcol = (tid & 15) * 4;      // 0..60

    float acc[4][4];
    #pragma unroll
    for (int i = 0; i < 4; i++)
        #pragma unroll
        for (int j = 0; j < 4; j++) acc[i][j] = 0.f;

    for (int k0 = 0; k0 < K; k0 += BKK) {
        float4 av = make_float4(0.f, 0.f, 0.f, 0.f);
        if (bm + arow < M)
            av = *reinterpret_cast<const float4*>(A + (size_t)(bm + arow) * K + k0 + acol);
        As[acol + 0][arow] = av.x;
        As[acol + 1][arow] = av.y;
        As[acol + 2][arow] = av.z;
        As[acol + 3][arow] = av.w;
        float4 bv = *reinterpret_cast<const float4*>(B + (size_t)(k0 + brow) * N + bn + bcol);
        *reinterpret_cast<float4*>(&Bs[brow][bcol]) = bv;
        __syncthreads();
        #pragma unroll
        for (int kk = 0; kk < BKK; kk++) {
            float4 a4 = *reinterpret_cast<const float4*>(&As[kk][ty * 4]);
            float4 b4 = *reinterpret_cast<const float4*>(&Bs[kk][tx * 4]);
            float a[4] = {a4.x, a4.y, a4.z, a4.w};
            float b[4] = {b4.x, b4.y, b4.z, b4.w};
            #pragma unroll
            for (int i = 0; i < 4; i++)
                #pragma unroll
                for (int j = 0; j < 4; j++)
                    acc[i][j] += a[i] * b[j];
        }
        __syncthreads();
    }

    #pragma unroll
    for (int i = 0; i < 4; i++) {
        int m = bm + ty * 4 + i;
        if (m >= M) continue;
        #pragma unroll
        for (int j = 0; j < 4; j++) {
            int n = bn + tx * 4 + j;
            float v = acc[i][j];
            if (bias) v += bias[n];
            if (!(flags & 1)) {
                if (resid) v += resid[(size_t)m * N + n];
                C[(size_t)m * N + n] = v;
            } else {
                if (resid) v += resid[(size_t)n * M + m];
                C[(size_t)n * M + m] = v;
            }
        }
    }
}

// ---------------- self-attention: flash style, 1 thread = 1 query row ---------
__global__ __launch_bounds__(64)
void attn_self_kernel(const float* __restrict__ q, const float* __restrict__ k,
                      const float* __restrict__ v, float* __restrict__ o)
{
    __shared__ float Ks[64 * 40];
    __shared__ float Vs[64 * 40];
    __shared__ float Sc[64 * 65];   // padded: (t*65+j)%32 distinct per t
    const int h  = blockIdx.y;
    const int q0 = blockIdx.x * 64;
    const int tid = threadIdx.x;

    float qr[40];
    #pragma unroll
    for (int d = 0; d < 40; d++)
        qr[d] = q[(size_t)(q0 + tid) * D_INNER + h * 40 + d] * ATT_SCALE;

    float m = -1e30f, l = 0.f;
    float accv[40];
    #pragma unroll
    for (int d = 0; d < 40; d++) accv[d] = 0.f;

    for (int t = 0; t < S_TOK; t += 64) {
        __syncthreads();
        for (int idx = tid; idx < 64 * 40; idx += 64) {
            int r = idx / 40;
            int d = idx - r * 40;
            size_t g = (size_t)(t + r) * D_INNER + h * 40 + d;
            Ks[idx] = k[g];
            Vs[idx] = v[g];
        }
        __syncthreads();

        float tmax = -1e30f;
        for (int j = 0; j < 64; j++) {
            float s = 0.f;
            #pragma unroll
            for (int d = 0; d < 40; d++) s += qr[d] * Ks[j * 40 + d];
            Sc[tid * 65 + j] = s;
            tmax = fmaxf(tmax, s);
        }
        float mnew = fmaxf(m, tmax);
        float corr = __expf(m - mnew);
        l *= corr;
        #pragma unroll
        for (int d = 0; d < 40; d++) accv[d] *= corr;
        for (int j = 0; j < 64; j++) {
            float p = __expf(Sc[tid * 65 + j] - mnew);
            l += p;
            #pragma unroll
            for (int d = 0; d < 40; d++) accv[d] += p * Vs[j * 40 + d];
        }
        m = mnew;
    }
    float inv = 1.f / l;
    #pragma unroll
    for (int d = 0; d < 40; d++)
        o[(size_t)(q0 + tid) * D_INNER + h * 40 + d] = accv[d] * inv;
}

// ---------------- cross-attention: 77 keys fit in smem -------------------------
__global__ __launch_bounds__(128)
void attn_cross_kernel(const float* __restrict__ q, const float* __restrict__ k2,
                       const float* __restrict__ v2, float* __restrict__ o)
{
    __shared__ float Ks[CTX_LEN * 40];
    __shared__ float Vs[CTX_LEN * 40];
    const int h  = blockIdx.y;
    const int q0 = blockIdx.x * 128;
    const int tid = threadIdx.x;

    for (int idx = tid; idx < CTX_LEN * 40; idx += 128) {
        int r = idx / 40;
        int d = idx - r * 40;
        Ks[idx] = k2[r * D_INNER + h * 40 + d];
        Vs[idx] = v2[r * D_INNER + h * 40 + d];
    }
    __syncthreads();

    float qr[40];
    #pragma unroll
    for (int d = 0; d < 40; d++)
        qr[d] = q[(size_t)(q0 + tid) * D_INNER + h * 40 + d] * ATT_SCALE;

    float m = -1e30f;
    for (int j = 0; j < CTX_LEN; j++) {
        float s = 0.f;
        #pragma unroll
        for (int d = 0; d < 40; d++) s += qr[d] * Ks[j * 40 + d];
        m = fmaxf(m, s);
    }
    float l = 0.f;
    float accv[40];
    #pragma unroll
    for (int d = 0; d < 40; d++) accv[d] = 0.f;
    for (int j = 0; j < CTX_LEN; j++) {
        float s = 0.f;
        #pragma unroll
        for (int d = 0; d < 40; d++) s += qr[d] * Ks[j * 40 + d];
        float p = __expf(s - m);
        l += p;
        #pragma unroll
        for (int d = 0; d < 40; d++) accv[d] += p * Vs[j * 40 + d];
    }
    float inv = 1.f / l;
    #pragma unroll
    for (int d = 0; d < 40; d++)
        o[(size_t)(q0 + tid) * D_INNER + h * 40 + d] = accv[d] * inv;
}

// ---------------- GEGLU: act = a * gelu_exact(g) -------------------------------
__global__ void geglu_kernel(const float* __restrict__ y, float* __restrict__ act)
{
    int idx = blockIdx.x * 256 + threadIdx.x;
    if (idx >= S_TOK * FF_HALF) return;
    int mrow = idx / FF_HALF;
    int j = idx - mrow * FF_HALF;
    float a = y[(size_t)mrow * FF_IN + j];
    float g = y[(size_t)mrow * FF_IN + FF_HALF + j];
    float ge = 0.5f * g * (1.f + erff(g * 0.70710678118654752f));
    act[idx] = a * ge;
}

// ---------------- host-side orchestration --------------------------------------
static inline void sgemm(const float* A, const float* B, const float* bias,
                         const float* resid, float* C, int M, int N, int K, int flags)
{
    dim3 grid(N / BN, (M + BM - 1) / BM);
    sgemm_kernel<<<grid, 256>>>(A, B, bias, resid, C, M, N, K, flags);
}

extern "C" void kernel_launch(void* const* d_in, const int* in_sizes, int n_in,
                              void* d_out, int out_size)
{
    const float* x          = (const float*)d_in[0];
    const float* context    = (const float*)d_in[1];
    const float* gn_scale   = (const float*)d_in[2];
    const float* gn_bias    = (const float*)d_in[3];
    const float* w_proj_in  = (const float*)d_in[4];
    const float* b_proj_in  = (const float*)d_in[5];
    const float* ln1_s      = (const float*)d_in[6];
    const float* ln1_b      = (const float*)d_in[7];
    const float* wq1        = (const float*)d_in[8];
    const float* wk1        = (const float*)d_in[9];
    const float* wv1        = (const float*)d_in[10];
    const float* wo1        = (const float*)d_in[11];
    const float* bo1        = (const float*)d_in[12];
    const float* ln2_s      = (const float*)d_in[13];
    const float* ln2_b      = (const float*)d_in[14];
    const float* wq2        = (const float*)d_in[15];
    const float* wk2        = (const float*)d_in[16];
    const float* wv2        = (const float*)d_in[17];
    const float* wo2        = (const float*)d_in[18];
    const float* bo2        = (const float*)d_in[19];
    const float* ln3_s      = (const float*)d_in[20];
    const float* ln3_b      = (const float*)d_in[21];
    const float* w_ff1      = (const float*)d_in[22];
    const float* b_ff1      = (const float*)d_in[23];
    const float* w_ff2      = (const float*)d_in[24];
    const float* b_ff2      = (const float*)d_in[25];
    const float* w_proj_out = (const float*)d_in[26];
    const float* b_proj_out = (const float*)d_in[27];
    float* out = (float*)d_out;

    float *gn, *h, *hn, *q, *k, *v, *attn, *ff, *act, *k2, *v2;
    cudaGetSymbolAddress((void**)&gn,   g_gn);
    cudaGetSymbolAddress((void**)&h,    g_h);
    cudaGetSymbolAddress((void**)&hn,   g_hn);
    cudaGetSymbolAddress((void**)&q,    g_q);
    cudaGetSymbolAddress((void**)&k,    g_k);
    cudaGetSymbolAddress((void**)&v,    g_v);
    cudaGetSymbolAddress((void**)&attn, g_attn);
    cudaGetSymbolAddress((void**)&ff,   g_ff);
    cudaGetSymbolAddress((void**)&act,  g_act);
    cudaGetSymbolAddress((void**)&k2,   g_k2);
    cudaGetSymbolAddress((void**)&v2,   g_v2);

    // GroupNorm + transpose to [s, c]
    groupnorm_kernel<<<32, 256>>>(x, gn_scale, gn_bias, gn);
    // proj_in -> h (residual trunk)
    sgemm(gn, w_proj_in, b_proj_in, nullptr, h, S_TOK, D_INNER, D_INNER, 0);

    // --- self attention ---
    layernorm_kernel<<<S_TOK / 8, 256>>>(h, ln1_s, ln1_b, hn);
    sgemm(hn, wq1, nullptr, nullptr, q, S_TOK, D_INNER, D_INNER, 0);
    sgemm(hn, wk1, nullptr, nullptr, k, S_TOK, D_INNER, D_INNER, 0);
    sgemm(hn, wv1, nullptr, nullptr, v, S_TOK, D_INNER, D_INNER, 0);
    attn_self_kernel<<<dim3(S_TOK / 64, HEADS), 64>>>(q, k, v, attn);
    sgemm(attn, wo1, bo1, h, h, S_TOK, D_INNER, D_INNER, 0);

    // --- cross attention ---
    layernorm_kernel<<<S_TOK / 8, 256>>>(h, ln2_s, ln2_b, hn);
    sgemm(hn, wq2, nullptr, nullptr, q, S_TOK, D_INNER, D_INNER, 0);
    sgemm(context, wk2, nullptr, nullptr, k2, CTX_LEN, D_INNER, CTX_DIM, 0);
    sgemm(context, wv2, nullptr, nullptr, v2, CTX_LEN, D_INNER, CTX_DIM, 0);
    attn_cross_kernel<<<dim3(S_TOK / 128, HEADS), 128>>>(q, k2, v2, attn);
    sgemm(attn, wo2, bo2, h, h, S_TOK, D_INNER, D_INNER, 0);

    // --- GEGLU feed forward ---
    layernorm_kernel<<<S_TOK / 8, 256>>>(h, ln3_s, ln3_b, hn);
    sgemm(hn, w_ff1, b_ff1, nullptr, ff, S_TOK, FF_IN, D_INNER, 0);
    geglu_kernel<<<(S_TOK * FF_HALF + 255) / 256, 256>>>(ff, act);
    sgemm(act, w_ff2, b_ff2, h, h, S_TOK, D_INNER, FF_HALF, 0);

    // --- proj_out, transposed store back to [c, s] + input residual ---
    sgemm(h, w_proj_out, b_proj_out, x, out, S_TOK, D_INNER, D_INNER, 1);
}

// round 2
// speedup vs baseline: 1.8731x; 1.8731x over previous
#include <cuda_runtime.h>
#include <math.h>
#include <stdint.h>

#define S_TOK   4096
#define D_INNER 320
#define HEADS   8
#define DHEAD   40
#define CTX_LEN 77
#define CTX_DIM 768
#define FF_IN   2560
#define FF_HALF 1280
#define ATT_SCALE 0.15811388300841897f

// ---------------- scratch ----------------
__device__ float g_gn  [S_TOK * D_INNER];
__device__ float g_h   [S_TOK * D_INNER];
__device__ float g_hn  [S_TOK * D_INNER];
__device__ float g_q   [S_TOK * D_INNER];
__device__ float g_k   [S_TOK * D_INNER];
__device__ float g_v   [S_TOK * D_INNER];
__device__ float g_attn[S_TOK * D_INNER];
__device__ float g_ff  [S_TOK * FF_IN];
__device__ float g_act [S_TOK * FF_HALF];
__device__ float g_k2  [CTX_LEN * D_INNER];
__device__ float g_v2  [CTX_LEN * D_INNER];

__device__ __forceinline__ float to_tf32(float x) {
    float r;
    asm("cvt.rna.tf32.f32 %0, %1;" : "=f"(r) : "f"(x));
    return r;
}

#define MMA_TF32(c, a, b) \
    asm volatile("mma.sync.aligned.m16n8k8.row.col.f32.tf32.tf32.f32 " \
                 "{%0,%1,%2,%3},{%4,%5,%6,%7},{%8,%9},{%0,%1,%2,%3};" \
                 : "+f"((c)[0]), "+f"((c)[1]), "+f"((c)[2]), "+f"((c)[3]) \
                 : "r"((a)[0]), "r"((a)[1]), "r"((a)[2]), "r"((a)[3]), \
                   "r"((b)[0]), "r"((b)[1]))

// ---------------- GroupNorm + transpose to [s,c] ----------------
__global__ void groupnorm_kernel(const float* __restrict__ x,
                                 const float* __restrict__ scale,
                                 const float* __restrict__ bias,
                                 float* __restrict__ outT)
{
    const int g = blockIdx.x;
    const int c0 = g * 10;
    const int N = 10 * S_TOK;
    __shared__ float ssum[256], ssq[256];
    float s = 0.f, sq = 0.f;
    for (int i = threadIdx.x; i < N; i += 256) {
        float v = x[c0 * S_TOK + i];
        s += v; sq += v * v;
    }
    ssum[threadIdx.x] = s; ssq[threadIdx.x] = sq;
    __syncthreads();
    for (int off = 128; off > 0; off >>= 1) {
        if (threadIdx.x < off) {
            ssum[threadIdx.x] += ssum[threadIdx.x + off];
            ssq[threadIdx.x]  += ssq[threadIdx.x + off];
        }
        __syncthreads();
    }
    __shared__ float smean, srstd;
    if (threadIdx.x == 0) {
        float mean = ssum[0] / (float)N;
        float var  = ssq[0] / (float)N - mean * mean;
        smean = mean;
        srstd = rsqrtf(var + 1e-6f);
    }
    __syncthreads();
    float mean = smean, rstd = srstd;
    for (int i = threadIdx.x; i < N; i += 256) {
        int c = c0 + i / S_TOK;
        int sp = i - (i / S_TOK) * S_TOK;
        float v = (x[c0 * S_TOK + i] - mean) * rstd * scale[c] + bias[c];
        outT[sp * D_INNER + c] = v;
    }
}

// ---------------- LayerNorm ----------------
__global__ void layernorm_kernel(const float* __restrict__ in,
                                 const float* __restrict__ s,
                                 const float* __restrict__ b,
                                 float* __restrict__ out)
{
    int row = blockIdx.x * 8 + (threadIdx.x >> 5);
    int lane = threadIdx.x & 31;
    const float* xr = in + row * D_INNER;
    float sum = 0.f, sq = 0.f;
    for (int i = lane; i < D_INNER; i += 32) {
        float v = xr[i];
        sum += v; sq += v * v;
    }
    #pragma unroll
    for (int off = 16; off > 0; off >>= 1) {
        sum += __shfl_xor_sync(0xffffffffu, sum, off);
        sq  += __shfl_xor_sync(0xffffffffu, sq,  off);
    }
    float mean = sum / (float)D_INNER;
    float var  = sq / (float)D_INNER - mean * mean;
    float rstd = rsqrtf(var + 1e-5f);
    for (int i = lane; i < D_INNER; i += 32)
        out[row * D_INNER + i] = (xr[i] - mean) * rstd * s[i] + b[i];
}

// ---------------- tf32 tensor-core GEMM: 128x64x16, 8 warps ----------------
// C = A(MxK)@B(KxN) [+bias] [+resid]; flags bit0 => transposed store C[n*M+m]
// requires: M%128==0, N%64==0, K%16==0
#define GBM 128
#define GBN 64
#define GBK 16
__global__ __launch_bounds__(256)
void gemm_tf32_kernel(const float* __restrict__ A, const float* __restrict__ B,
                      const float* __restrict__ bias, const float* __restrict__ resid,
                      float* __restrict__ C, int M, int N, int K, int flags)
{
    __shared__ float As[GBK][GBM + 4];
    __shared__ float Bs[GBK][GBN + 4];
    const int bm = blockIdx.y * GBM;
    const int bn = blockIdx.x * GBN;
    const int tid = threadIdx.x;
    const int warp = tid >> 5, lane = tid & 31;
    const int wm = (warp >> 1) * 32, wn = (warp & 1) * 32;
    const int gid = lane >> 2, tig = lane & 3;

    const int ar = tid >> 1;
    const int ak = (tid & 1) * 8;
    const int bk = tid >> 4;
    const int bc = (tid & 15) * 4;

    float c[2][4][4];
    #pragma unroll
    for (int i = 0; i < 2; i++)
        #pragma unroll
        for (int j = 0; j < 4; j++)
            #pragma unroll
            for (int t = 0; t < 4; t++) c[i][j][t] = 0.f;

    for (int k0 = 0; k0 < K; k0 += GBK) {
        float4 av0 = *reinterpret_cast<const float4*>(A + (size_t)(bm + ar) * K + k0 + ak);
        float4 av1 = *reinterpret_cast<const float4*>(A + (size_t)(bm + ar) * K + k0 + ak + 4);
        As[ak + 0][ar] = to_tf32(av0.x);
        As[ak + 1][ar] = to_tf32(av0.y);
        As[ak + 2][ar] = to_tf32(av0.z);
        As[ak + 3][ar] = to_tf32(av0.w);
        As[ak + 4][ar] = to_tf32(av1.x);
        As[ak + 5][ar] = to_tf32(av1.y);
        As[ak + 6][ar] = to_tf32(av1.z);
        As[ak + 7][ar] = to_tf32(av1.w);
        float4 bv = *reinterpret_cast<const float4*>(B + (size_t)(k0 + bk) * N + bn + bc);
        Bs[bk][bc + 0] = to_tf32(bv.x);
        Bs[bk][bc + 1] = to_tf32(bv.y);
        Bs[bk][bc + 2] = to_tf32(bv.z);
        Bs[bk][bc + 3] = to_tf32(bv.w);
        __syncthreads();

        #pragma unroll
        for (int ks = 0; ks < GBK; ks += 8) {
            uint32_t af[2][4], bf[4][2];
            #pragma unroll
            for (int mt = 0; mt < 2; mt++) {
                int m0 = wm + mt * 16;
                af[mt][0] = __float_as_uint(As[ks + tig][m0 + gid]);
                af[mt][1] = __float_as_uint(As[ks + tig][m0 + 8 + gid]);
                af[mt][2] = __float_as_uint(As[ks + 4 + tig][m0 + gid]);
                af[mt][3] = __float_as_uint(As[ks + 4 + tig][m0 + 8 + gid]);
            }
            #pragma unroll
            for (int nt = 0; nt < 4; nt++) {
                int n0 = wn + nt * 8;
                bf[nt][0] = __float_as_uint(Bs[ks + tig][n0 + gid]);
                bf[nt][1] = __float_as_uint(Bs[ks + 4 + tig][n0 + gid]);
            }
            #pragma unroll
            for (int mt = 0; mt < 2; mt++)
                #pragma unroll
                for (int nt = 0; nt < 4; nt++)
                    MMA_TF32(c[mt][nt], af[mt], bf[nt]);
        }
        __syncthreads();
    }

    #pragma unroll
    for (int mt = 0; mt < 2; mt++) {
        int r0 = bm + wm + mt * 16 + gid;
        int r1 = r0 + 8;
        #pragma unroll
        for (int nt = 0; nt < 4; nt++) {
            int col = bn + wn + nt * 8 + tig * 2;
            float v00 = c[mt][nt][0], v01 = c[mt][nt][1];
            float v10 = c[mt][nt][2], v11 = c[mt][nt][3];
            if (bias) {
                float b0 = bias[col], b1 = bias[col + 1];
                v00 += b0; v01 += b1; v10 += b0; v11 += b1;
            }
            if (!(flags & 1)) {
                if (resid) {
                    v00 += resid[(size_t)r0 * N + col];
                    v01 += resid[(size_t)r0 * N + col + 1];
                    v10 += resid[(size_t)r1 * N + col];
                    v11 += resid[(size_t)r1 * N + col + 1];
                }
                C[(size_t)r0 * N + col]     = v00;
                C[(size_t)r0 * N + col + 1] = v01;
                C[(size_t)r1 * N + col]     = v10;
                C[(size_t)r1 * N + col + 1] = v11;
            } else {
                if (resid) {
                    v00 += resid[(size_t)col * M + r0];
                    v01 += resid[(size_t)(col + 1) * M + r0];
                    v10 += resid[(size_t)col * M + r1];
                    v11 += resid[(size_t)(col + 1) * M + r1];
                }
                C[(size_t)col * M + r0]       = v00;
                C[(size_t)(col + 1) * M + r0] = v01;
                C[(size_t)col * M + r1]       = v10;
                C[(size_t)(col + 1) * M + r1] = v11;
            }
        }
    }
}

// ---------------- fp32 SGEMM for small M (cross-attn K/V: M=77) ----------------
#define BM 64
#define BN 64
#define BKK 16
__global__ __launch_bounds__(256)
void sgemm_kernel(const float* __restrict__ A, const float* __restrict__ B,
                  const float* __restrict__ bias, const float* __restrict__ resid,
                  float* __restrict__ C, int M, int N, int K, int flags)
{
    __shared__ float As[BKK][BM];
    __shared__ float Bs[BKK][BN];
    const int bm = blockIdx.y * BM;
    const int bn = blockIdx.x * BN;
    const int tid = threadIdx.x;
    const int tx = tid & 15;
    const int ty = tid >> 4;
    const int arow = tid >> 2;
    const int acol = (tid & 3) * 4;
    const int brow = tid >> 4;
    const int bcol = (tid & 15) * 4;

    float acc[4][4];
    #pragma unroll
    for (int i = 0; i < 4; i++)
        #pragma unroll
        for (int j = 0; j < 4; j++) acc[i][j] = 0.f;

    for (int k0 = 0; k0 < K; k0 += BKK) {
        float4 av = make_float4(0.f, 0.f, 0.f, 0.f);
        if (bm + arow < M)
            av = *reinterpret_cast<const float4*>(A + (size_t)(bm + arow) * K + k0 + acol);
        As[acol + 0][arow] = av.x;
        As[acol + 1][arow] = av.y;
        As[acol + 2][arow] = av.z;
        As[acol + 3][arow] = av.w;
        float4 bv = *reinterpret_cast<const float4*>(B + (size_t)(k0 + brow) * N + bn + bcol);
        *reinterpret_cast<float4*>(&Bs[brow][bcol]) = bv;
        __syncthreads();
        #pragma unroll
        for (int kk = 0; kk < BKK; kk++) {
            float4 a4 = *reinterpret_cast<const float4*>(&As[kk][ty * 4]);
            float4 b4 = *reinterpret_cast<const float4*>(&Bs[kk][tx * 4]);
            float a[4] = {a4.x, a4.y, a4.z, a4.w};
            float b[4] = {b4.x, b4.y, b4.z, b4.w};
            #pragma unroll
            for (int i = 0; i < 4; i++)
                #pragma unroll
                for (int j = 0; j < 4; j++)
                    acc[i][j] += a[i] * b[j];
        }
        __syncthreads();
    }

    #pragma unroll
    for (int i = 0; i < 4; i++) {
        int m = bm + ty * 4 + i;
        if (m >= M) continue;
        #pragma unroll
        for (int j = 0; j < 4; j++) {
            int n = bn + tx * 4 + j;
            float v = acc[i][j];
            if (bias) v += bias[n];
            if (!(flags & 1)) {
                if (resid) v += resid[(size_t)m * N + n];
                C[(size_t)m * N + n] = v;
            } else {
                if (resid) v += resid[(size_t)n * M + m];
                C[(size_t)n * M + m] = v;
            }
        }
    }
}

// ---------------- self-attention: flash, tf32 tensor cores ----------------
// block = (64 queries, 1 head), 4 warps; warp w owns rows [w*16, w*16+16)
__global__ __launch_bounds__(128)
void attn_self_tc_kernel(const float* __restrict__ q, const float* __restrict__ k,
                         const float* __restrict__ v, float* __restrict__ o)
{
    __shared__ float Ks[64][44];
    __shared__ float Vs[64][44];
    __shared__ float Ss[64][68];
    __shared__ float m_s[64], l_s[64], corr_s[64];

    const int h = blockIdx.y;
    const int q0 = blockIdx.x * 64;
    const int tid = threadIdx.x;
    const int warp = tid >> 5, lane = tid & 31;
    const int gid = lane >> 2, tig = lane & 3;

    // Q fragments in registers (scaled + tf32), 5 k-steps of 8
    uint32_t qf[5][4];
    {
        const float* qp0 = q + (size_t)(q0 + warp * 16 + gid) * D_INNER + h * 40;
        const float* qp1 = q + (size_t)(q0 + warp * 16 + 8 + gid) * D_INNER + h * 40;
        #pragma unroll
        for (int ks = 0; ks < 5; ks++) {
            qf[ks][0] = __float_as_uint(to_tf32(qp0[ks * 8 + tig] * ATT_SCALE));
            qf[ks][1] = __float_as_uint(to_tf32(qp1[ks * 8 + tig] * ATT_SCALE));
            qf[ks][2] = __float_as_uint(to_tf32(qp0[ks * 8 + tig + 4] * ATT_SCALE));
            qf[ks][3] = __float_as_uint(to_tf32(qp1[ks * 8 + tig + 4] * ATT_SCALE));
        }
    }

    float oacc[5][4];
    #pragma unroll
    for (int nt = 0; nt < 5; nt++)
        #pragma unroll
        for (int t = 0; t < 4; t++) oacc[nt][t] = 0.f;

    if (tid < 64) { m_s[tid] = -1e30f; l_s[tid] = 0.f; }

    for (int t0 = 0; t0 < S_TOK; t0 += 64) {
        __syncthreads();   // Ks/Vs free (prior PV done), m/l init visible
        // load K,V tile (64x40 each), tf32-convert
        for (int i = tid; i < 640; i += 128) {
            int row = i / 10;
            int c4 = (i - row * 10) * 4;
            size_t gidx = (size_t)(t0 + row) * D_INNER + h * 40 + c4;
            float4 kv = *reinterpret_cast<const float4*>(k + gidx);
            Ks[row][c4 + 0] = to_tf32(kv.x);
            Ks[row][c4 + 1] = to_tf32(kv.y);
            Ks[row][c4 + 2] = to_tf32(kv.z);
            Ks[row][c4 + 3] = to_tf32(kv.w);
            float4 vv = *reinterpret_cast<const float4*>(v + gidx);
            Vs[row][c4 + 0] = to_tf32(vv.x);
            Vs[row][c4 + 1] = to_tf32(vv.y);
            Vs[row][c4 + 2] = to_tf32(vv.z);
            Vs[row][c4 + 3] = to_tf32(vv.w);
        }
        __syncthreads();

        // S = Q @ K^T  (warp: 16 rows x 64 cols)
        #pragma unroll
        for (int nt = 0; nt < 8; nt++) {
            float sc[4] = {0.f, 0.f, 0.f, 0.f};
            #pragma unroll
            for (int ks = 0; ks < 5; ks++) {
                uint32_t bf[2];
                bf[0] = __float_as_uint(Ks[nt * 8 + gid][ks * 8 + tig]);
                bf[1] = __float_as_uint(Ks[nt * 8 + gid][ks * 8 + tig + 4]);
                MMA_TF32(sc, qf[ks], bf);
            }
            int r = warp * 16 + gid;
            Ss[r][nt * 8 + tig * 2]         = sc[0];
            Ss[r][nt * 8 + tig * 2 + 1]     = sc[1];
            Ss[r + 8][nt * 8 + tig * 2]     = sc[2];
            Ss[r + 8][nt * 8 + tig * 2 + 1] = sc[3];
        }
        __syncthreads();

        // online softmax: 2 threads per row, 32 cols each
        {
            int row = tid >> 1;
            int cb = (tid & 1) * 32;
            float tmax = -1e30f;
            #pragma unroll
            for (int j = 0; j < 32; j++) tmax = fmaxf(tmax, Ss[row][cb + j]);
            tmax = fmaxf(tmax, __shfl_xor_sync(0xffffffffu, tmax, 1));
            float mold = m_s[row];
            float mnew = fmaxf(mold, tmax);
            float corr = __expf(mold - mnew);
            float lsum = 0.f;
            #pragma unroll
            for (int j = 0; j < 32; j++) {
                float p = __expf(Ss[row][cb + j] - mnew);
                lsum += p;
                Ss[row][cb + j] = to_tf32(p);
            }
            lsum += __shfl_xor_sync(0xffffffffu, lsum, 1);
            if ((tid & 1) == 0) {
                m_s[row] = mnew;
                l_s[row] = l_s[row] * corr + lsum;
                corr_s[row] = corr;
            }
        }
        __syncthreads();

        // O = O*corr + P @ V
        float corr0 = corr_s[warp * 16 + gid];
        float corr1 = corr_s[warp * 16 + 8 + gid];
        #pragma unroll
        for (int nt = 0; nt < 5; nt++) {
            oacc[nt][0] *= corr0; oacc[nt][1] *= corr0;
            oacc[nt][2] *= corr1; oacc[nt][3] *= corr1;
        }
        #pragma unroll
        for (int ks = 0; ks < 8; ks++) {
            uint32_t af[4];
            int r = warp * 16 + gid;
            af[0] = __float_as_uint(Ss[r][ks * 8 + tig]);
            af[1] = __float_as_uint(Ss[r + 8][ks * 8 + tig]);
            af[2] = __float_as_uint(Ss[r][ks * 8 + tig + 4]);
            af[3] = __float_as_uint(Ss[r + 8][ks * 8 + tig + 4]);
            #pragma unroll
            for (int nt = 0; nt < 5; nt++) {
                uint32_t bf[2];
                bf[0] = __float_as_uint(Vs[ks * 8 + tig][nt * 8 + gid]);
                bf[1] = __float_as_uint(Vs[ks * 8 + tig + 4][nt * 8 + gid]);
                MMA_TF32(oacc[nt], af, bf);
            }
        }
    }

    float inv0 = 1.f / l_s[warp * 16 + gid];
    float inv1 = 1.f / l_s[warp * 16 + 8 + gid];
    size_t base0 = (size_t)(q0 + warp * 16 + gid) * D_INNER + h * 40;
    size_t base1 = (size_t)(q0 + warp * 16 + 8 + gid) * D_INNER + h * 40;
    #pragma unroll
    for (int nt = 0; nt < 5; nt++) {
        int col = nt * 8 + tig * 2;
        o[base0 + col]     = oacc[nt][0] * inv0;
        o[base0 + col + 1] = oacc[nt][1] * inv0;
        o[base1 + col]     = oacc[nt][2] * inv1;
        o[base1 + col + 1] = oacc[nt][3] * inv1;
    }
}

// ---------------- cross-attention (77 keys, fp32) ----------------
__global__ __launch_bounds__(128)
void attn_cross_kernel(const float* __restrict__ q, const float* __restrict__ k2,
                       const float* __restrict__ v2, float* __restrict__ o)
{
    __shared__ float Ks[CTX_LEN * 40];
    __shared__ float Vs[CTX_LEN * 40];
    const int h  = blockIdx.y;
    const int q0 = blockIdx.x * 128;
    const int tid = threadIdx.x;

    for (int idx = tid; idx < CTX_LEN * 40; idx += 128) {
        int r = idx / 40;
        int d = idx - r * 40;
        Ks[idx] = k2[r * D_INNER + h * 40 + d];
        Vs[idx] = v2[r * D_INNER + h * 40 + d];
    }
    __syncthreads();

    float qr[40];
    #pragma unroll
    for (int d = 0; d < 40; d++)
        qr[d] = q[(size_t)(q0 + tid) * D_INNER + h * 40 + d] * ATT_SCALE;

    float m = -1e30f;
    for (int j = 0; j < CTX_LEN; j++) {
        float s = 0.f;
        #pragma unroll
        for (int d = 0; d < 40; d++) s += qr[d] * Ks[j * 40 + d];
        m = fmaxf(m, s);
    }
    float l = 0.f;
    float accv[40];
    #pragma unroll
    for (int d = 0; d < 40; d++) accv[d] = 0.f;
    for (int j = 0; j < CTX_LEN; j++) {
        float s = 0.f;
        #pragma unroll
        for (int d = 0; d < 40; d++) s += qr[d] * Ks[j * 40 + d];
        float p = __expf(s - m);
        l += p;
        #pragma unroll
        for (int d = 0; d < 40; d++) accv[d] += p * Vs[j * 40 + d];
    }
    float inv = 1.f / l;
    #pragma unroll
    for (int d = 0; d < 40; d++)
        o[(size_t)(q0 + tid) * D_INNER + h * 40 + d] = accv[d] * inv;
}

// ---------------- GEGLU ----------------
__global__ void geglu_kernel(const float* __restrict__ y, float* __restrict__ act)
{
    int idx = blockIdx.x * 256 + threadIdx.x;
    if (idx >= S_TOK * FF_HALF) return;
    int mrow = idx / FF_HALF;
    int j = idx - mrow * FF_HALF;
    float a = y[(size_t)mrow * FF_IN + j];
    float g = y[(size_t)mrow * FF_IN + FF_HALF + j];
    float ge = 0.5f * g * (1.f + erff(g * 0.70710678118654752f));
    act[idx] = a * ge;
}

// ---------------- host ----------------
static inline void gemm_tc(const float* A, const float* B, const float* bias,
                           const float* resid, float* C, int M, int N, int K, int flags)
{
    dim3 grid(N / GBN, M / GBM);
    gemm_tf32_kernel<<<grid, 256>>>(A, B, bias, resid, C, M, N, K, flags);
}

static inline void sgemm(const float* A, const float* B, const float* bias,
                         const float* resid, float* C, int M, int N, int K, int flags)
{
    dim3 grid(N / BN, (M + BM - 1) / BM);
    sgemm_kernel<<<grid, 256>>>(A, B, bias, resid, C, M, N, K, flags);
}

extern "C" void kernel_launch(void* const* d_in, const int* in_sizes, int n_in,
                              void* d_out, int out_size)
{
    const float* x          = (const float*)d_in[0];
    const float* context    = (const float*)d_in[1];
    const float* gn_scale   = (const float*)d_in[2];
    const float* gn_bias    = (const float*)d_in[3];
    const float* w_proj_in  = (const float*)d_in[4];
    const float* b_proj_in  = (const float*)d_in[5];
    const float* ln1_s      = (const float*)d_in[6];
    const float* ln1_b      = (const float*)d_in[7];
    const float* wq1        = (const float*)d_in[8];
    const float* wk1        = (const float*)d_in[9];
    const float* wv1        = (const float*)d_in[10];
    const float* wo1        = (const float*)d_in[11];
    const float* bo1        = (const float*)d_in[12];
    const float* ln2_s      = (const float*)d_in[13];
    const float* ln2_b      = (const float*)d_in[14];
    const float* wq2        = (const float*)d_in[15];
    const float* wk2        = (const float*)d_in[16];
    const float* wv2        = (const float*)d_in[17];
    const float* wo2        = (const float*)d_in[18];
    const float* bo2        = (const float*)d_in[19];
    const float* ln3_s      = (const float*)d_in[20];
    const float* ln3_b      = (const float*)d_in[21];
    const float* w_ff1      = (const float*)d_in[22];
    const float* b_ff1      = (const float*)d_in[23];
    const float* w_ff2      = (const float*)d_in[24];
    const float* b_ff2      = (const float*)d_in[25];
    const float* w_proj_out = (const float*)d_in[26];
    const float* b_proj_out = (const float*)d_in[27];
    float* out = (float*)d_out;

    float *gn, *h, *hn, *q, *k, *v, *attn, *ff, *act, *k2, *v2;
    cudaGetSymbolAddress((void**)&gn,   g_gn);
    cudaGetSymbolAddress((void**)&h,    g_h);
    cudaGetSymbolAddress((void**)&hn,   g_hn);
    cudaGetSymbolAddress((void**)&q,    g_q);
    cudaGetSymbolAddress((void**)&k,    g_k);
    cudaGetSymbolAddress((void**)&v,    g_v);
    cudaGetSymbolAddress((void**)&attn, g_attn);
    cudaGetSymbolAddress((void**)&ff,   g_ff);
    cudaGetSymbolAddress((void**)&act,  g_act);
    cudaGetSymbolAddress((void**)&k2,   g_k2);
    cudaGetSymbolAddress((void**)&v2,   g_v2);

    groupnorm_kernel<<<32, 256>>>(x, gn_scale, gn_bias, gn);
    gemm_tc(gn, w_proj_in, b_proj_in, nullptr, h, S_TOK, D_INNER, D_INNER, 0);

    // --- self attention ---
    layernorm_kernel<<<S_TOK / 8, 256>>>(h, ln1_s, ln1_b, hn);
    gemm_tc(hn, wq1, nullptr, nullptr, q, S_TOK, D_INNER, D_INNER, 0);
    gemm_tc(hn, wk1, nullptr, nullptr, k, S_TOK, D_INNER, D_INNER, 0);
    gemm_tc(hn, wv1, nullptr, nullptr, v, S_TOK, D_INNER, D_INNER, 0);
    attn_self_tc_kernel<<<dim3(S_TOK / 64, HEADS), 128>>>(q, k, v, attn);
    gemm_tc(attn, wo1, bo1, h, h, S_TOK, D_INNER, D_INNER, 0);

    // --- cross attention ---
    layernorm_kernel<<<S_TOK / 8, 256>>>(h, ln2_s, ln2_b, hn);
    gemm_tc(hn, wq2, nullptr, nullptr, q, S_TOK, D_INNER, D_INNER, 0);
    sgemm(context, wk2, nullptr, nullptr, k2, CTX_LEN, D_INNER, CTX_DIM, 0);
    sgemm(context, wv2, nullptr, nullptr, v2, CTX_LEN, D_INNER, CTX_DIM, 0);
    attn_cross_kernel<<<dim3(S_TOK / 128, HEADS), 128>>>(q, k2, v2, attn);
    gemm_tc(attn, wo2, bo2, h, h, S_TOK, D_INNER, D_INNER, 0);

    // --- GEGLU feed forward ---
    layernorm_kernel<<<S_TOK / 8, 256>>>(h, ln3_s, ln3_b, hn);
    gemm_tc(hn, w_ff1, b_ff1, nullptr, ff, S_TOK, FF_IN, D_INNER, 0);
    geglu_kernel<<<(S_TOK * FF_HALF + 255) / 256, 256>>>(ff, act);
    gemm_tc(act, w_ff2, b_ff2, h, h, S_TOK, D_INNER, FF_HALF, 0);

    // --- proj_out (transposed store) + input residual ---
    gemm_tc(h, w_proj_out, b_proj_out, x, out, S_TOK, D_INNER, D_INNER, 1);
}

// round 3
// speedup vs baseline: 2.6903x; 1.4363x over previous
#include <cuda_runtime.h>
#include <math.h>
#include <stdint.h>

#define S_TOK   4096
#define D_INNER 320
#define HEADS   8
#define DHEAD   40
#define CTX_LEN 77
#define CTX_DIM 768
#define FF_IN   2560
#define FF_HALF 1280
#define ATT_SCALE 0.15811388300841897f

// ---------------- scratch ----------------
__device__ float g_gn  [S_TOK * D_INNER];
__device__ float g_h   [S_TOK * D_INNER];
__device__ float g_hn  [S_TOK * D_INNER];
__device__ float g_q   [S_TOK * D_INNER];
__device__ float g_k   [S_TOK * D_INNER];
__device__ float g_v   [S_TOK * D_INNER];
__device__ float g_attn[S_TOK * D_INNER];
__device__ float g_ff  [S_TOK * FF_IN];
__device__ float g_act [S_TOK * FF_HALF];
__device__ float g_k2  [CTX_LEN * D_INNER];
__device__ float g_v2  [CTX_LEN * D_INNER];

__device__ __forceinline__ float to_tf32(float x) {
    float r;
    asm("cvt.rna.tf32.f32 %0, %1;" : "=f"(r) : "f"(x));
    return r;
}

#define MMA_TF32(c, a, b) \
    asm volatile("mma.sync.aligned.m16n8k8.row.col.f32.tf32.tf32.f32 " \
                 "{%0,%1,%2,%3},{%4,%5,%6,%7},{%8,%9},{%0,%1,%2,%3};" \
                 : "+f"((c)[0]), "+f"((c)[1]), "+f"((c)[2]), "+f"((c)[3]) \
                 : "r"((a)[0]), "r"((a)[1]), "r"((a)[2]), "r"((a)[3]), \
                   "r"((b)[0]), "r"((b)[1]))

__device__ __forceinline__ void cp_async16(uint32_t s, const void* g) {
    asm volatile("cp.async.cg.shared.global [%0], [%1], 16;" :: "r"(s), "l"(g));
}
__device__ __forceinline__ void cp_commit() {
    asm volatile("cp.async.commit_group;");
}
template<int W> __device__ __forceinline__ void cp_wait() {
    asm volatile("cp.async.wait_group %0;" :: "n"(W));
}

// ---------------- GroupNorm + transpose to [s,c] ----------------
__global__ void groupnorm_kernel(const float* __restrict__ x,
                                 const float* __restrict__ scale,
                                 const float* __restrict__ bias,
                                 float* __restrict__ outT)
{
    const int g = blockIdx.x;
    const int c0 = g * 10;
    const int N = 10 * S_TOK;
    __shared__ float ssum[256], ssq[256];
    float s = 0.f, sq = 0.f;
    for (int i = threadIdx.x; i < N; i += 256) {
        float v = x[c0 * S_TOK + i];
        s += v; sq += v * v;
    }
    ssum[threadIdx.x] = s; ssq[threadIdx.x] = sq;
    __syncthreads();
    for (int off = 128; off > 0; off >>= 1) {
        if (threadIdx.x < off) {
            ssum[threadIdx.x] += ssum[threadIdx.x + off];
            ssq[threadIdx.x]  += ssq[threadIdx.x + off];
        }
        __syncthreads();
    }
    __shared__ float smean, srstd;
    if (threadIdx.x == 0) {
        float mean = ssum[0] / (float)N;
        float var  = ssq[0] / (float)N - mean * mean;
        smean = mean;
        srstd = rsqrtf(var + 1e-6f);
    }
    __syncthreads();
    float mean = smean, rstd = srstd;
    for (int i = threadIdx.x; i < N; i += 256) {
        int c = c0 + i / S_TOK;
        int sp = i - (i / S_TOK) * S_TOK;
        float v = (x[c0 * S_TOK + i] - mean) * rstd * scale[c] + bias[c];
        outT[sp * D_INNER + c] = v;
    }
}

// ---------------- LayerNorm ----------------
__global__ void layernorm_kernel(const float* __restrict__ in,
                                 const float* __restrict__ s,
                                 const float* __restrict__ b,
                                 float* __restrict__ out)
{
    int row = blockIdx.x * 8 + (threadIdx.x >> 5);
    int lane = threadIdx.x & 31;
    const float* xr = in + row * D_INNER;
    float sum = 0.f, sq = 0.f;
    for (int i = lane; i < D_INNER; i += 32) {
        float v = xr[i];
        sum += v; sq += v * v;
    }
    #pragma unroll
    for (int off = 16; off > 0; off >>= 1) {
        sum += __shfl_xor_sync(0xffffffffu, sum, off);
        sq  += __shfl_xor_sync(0xffffffffu, sq,  off);
    }
    float mean = sum / (float)D_INNER;
    float var  = sq / (float)D_INNER - mean * mean;
    float rstd = rsqrtf(var + 1e-5f);
    for (int i = lane; i < D_INNER; i += 32)
        out[row * D_INNER + i] = (xr[i] - mean) * rstd * s[i] + b[i];
}

// ---------------- tf32 GEMM core: 64x64x32, 128 threads, cp.async 2-stage -----
// requires M%64==0, N%64==0, K%32==0
#define GBM 64
#define GBN 64
#define GBK 32

__device__ __forceinline__ void gemm_core(
    const float* __restrict__ A, const float* __restrict__ B,
    const float* __restrict__ bias, const float* __restrict__ resid,
    float* __restrict__ C, int M, int N, int K, int flags, int bm, int bn)
{
    __shared__ float As[2][GBM][GBK + 4];   // stride 36
    __shared__ float Bs[2][GBK][GBN + 4];   // stride 68
    const int tid = threadIdx.x;
    const int warp = tid >> 5, lane = tid & 31;
    const int wm = (warp >> 1) * 32, wn = (warp & 1) * 32;
    const int gid = lane >> 2, tig = lane & 3;

    float c[2][4][4];
    #pragma unroll
    for (int i = 0; i < 2; i++)
        #pragma unroll
        for (int j = 0; j < 4; j++)
            #pragma unroll
            for (int t = 0; t < 4; t++) c[i][j][t] = 0.f;

    const int nk = K / GBK;

    // stage loader
    auto load_stage = [&](int s, int k0) {
        #pragma unroll
        for (int i = 0; i < 4; i++) {
            int idx = tid + i * 128;
            int r = idx >> 3, c4 = (idx & 7) * 4;
            cp_async16((uint32_t)__cvta_generic_to_shared(&As[s][r][c4]),
                       A + (size_t)(bm + r) * K + k0 + c4);
        }
        #pragma unroll
        for (int i = 0; i < 4; i++) {
            int idx = tid + i * 128;
            int r = idx >> 4, c4 = (idx & 15) * 4;
            cp_async16((uint32_t)__cvta_generic_to_shared(&Bs[s][r][c4]),
                       B + (size_t)(k0 + r) * N + bn + c4);
        }
        cp_commit();
    };

    load_stage(0, 0);

    for (int t = 0; t < nk; t++) {
        int s = t & 1;
        if (t + 1 < nk) {
            load_stage(s ^ 1, (t + 1) * GBK);
            cp_wait<1>();
        } else {
            cp_wait<0>();
        }
        __syncthreads();

        #pragma unroll
        for (int ks = 0; ks < GBK; ks += 8) {
            uint32_t af[2][4], bf[4][2];
            #pragma unroll
            for (int mt = 0; mt < 2; mt++) {
                int m0 = wm + mt * 16;
                af[mt][0] = __float_as_uint(As[s][m0 + gid][ks + tig]);
                af[mt][1] = __float_as_uint(As[s][m0 + 8 + gid][ks + tig]);
                af[mt][2] = __float_as_uint(As[s][m0 + gid][ks + tig + 4]);
                af[mt][3] = __float_as_uint(As[s][m0 + 8 + gid][ks + tig + 4]);
            }
            #pragma unroll
            for (int nt = 0; nt < 4; nt++) {
                int n0 = wn + nt * 8;
                bf[nt][0] = __float_as_uint(Bs[s][ks + tig][n0 + gid]);
                bf[nt][1] = __float_as_uint(Bs[s][ks + tig + 4][n0 + gid]);
            }
            #pragma unroll
            for (int mt = 0; mt < 2; mt++)
                #pragma unroll
                for (int nt = 0; nt < 4; nt++)
                    MMA_TF32(c[mt][nt], af[mt], bf[nt]);
        }
        __syncthreads();
    }

    #pragma unroll
    for (int mt = 0; mt < 2; mt++) {
        int r0 = bm + wm + mt * 16 + gid;
        int r1 = r0 + 8;
        #pragma unroll
        for (int nt = 0; nt < 4; nt++) {
            int col = bn + wn + nt * 8 + tig * 2;
            float v00 = c[mt][nt][0], v01 = c[mt][nt][1];
            float v10 = c[mt][nt][2], v11 = c[mt][nt][3];
            if (bias) {
                float b0 = bias[col], b1 = bias[col + 1];
                v00 += b0; v01 += b1; v10 += b0; v11 += b1;
            }
            if (!(flags & 1)) {
                if (resid) {
                    v00 += resid[(size_t)r0 * N + col];
                    v01 += resid[(size_t)r0 * N + col + 1];
                    v10 += resid[(size_t)r1 * N + col];
                    v11 += resid[(size_t)r1 * N + col + 1];
                }
                C[(size_t)r0 * N + col]     = v00;
                C[(size_t)r0 * N + col + 1] = v01;
                C[(size_t)r1 * N + col]     = v10;
                C[(size_t)r1 * N + col + 1] = v11;
            } else {
                if (resid) {
                    v00 += resid[(size_t)col * M + r0];
                    v01 += resid[(size_t)(col + 1) * M + r0];
                    v10 += resid[(size_t)col * M + r1];
                    v11 += resid[(size_t)(col + 1) * M + r1];
                }
                C[(size_t)col * M + r0]       = v00;
                C[(size_t)(col + 1) * M + r0] = v01;
                C[(size_t)col * M + r1]       = v10;
                C[(size_t)(col + 1) * M + r1] = v11;
            }
        }
    }
}

__global__ __launch_bounds__(128)
void gemm_tf32_kernel(const float* __restrict__ A, const float* __restrict__ B,
                      const float* __restrict__ bias, const float* __restrict__ resid,
                      float* __restrict__ C, int M, int N, int K, int flags)
{
    gemm_core(A, B, bias, resid, C, M, N, K, flags,
              blockIdx.y * GBM, blockIdx.x * GBN);
}

// fused QKV: grid.z picks (B, C) pair; A shared across z
__global__ __launch_bounds__(128)
void gemm_qkv_kernel(const float* __restrict__ A,
                     const float* __restrict__ B0, const float* __restrict__ B1,
                     const float* __restrict__ B2,
                     float* __restrict__ C0, float* __restrict__ C1,
                     float* __restrict__ C2, int M, int N, int K)
{
    const float* B = (blockIdx.z == 0) ? B0 : (blockIdx.z == 1) ? B1 : B2;
    float* C       = (blockIdx.z == 0) ? C0 : (blockIdx.z == 1) ? C1 : C2;
    gemm_core(A, B, nullptr, nullptr, C, M, N, K, 0,
              blockIdx.y * GBM, blockIdx.x * GBN);
}

// ---------------- fp32 SGEMM for small M (ctx K/V) ----------------
#define BM 64
#define BN 64
#define BKK 16
__global__ __launch_bounds__(256)
void sgemm_kernel(const float* __restrict__ A, const float* __restrict__ B,
                  float* __restrict__ C, int M, int N, int K)
{
    __shared__ float As[BKK][BM];
    __shared__ float Bs[BKK][BN];
    const int bm = blockIdx.y * BM;
    const int bn = blockIdx.x * BN;
    const int tid = threadIdx.x;
    const int tx = tid & 15;
    const int ty = tid >> 4;
    const int arow = tid >> 2;
    const int acol = (tid & 3) * 4;
    const int brow = tid >> 4;
    const int bcol = (tid & 15) * 4;

    float acc[4][4];
    #pragma unroll
    for (int i = 0; i < 4; i++)
        #pragma unroll
        for (int j = 0; j < 4; j++) acc[i][j] = 0.f;

    for (int k0 = 0; k0 < K; k0 += BKK) {
        float4 av = make_float4(0.f, 0.f, 0.f, 0.f);
        if (bm + arow < M)
            av = *reinterpret_cast<const float4*>(A + (size_t)(bm + arow) * K + k0 + acol);
        As[acol + 0][arow] = av.x;
        As[acol + 1][arow] = av.y;
        As[acol + 2][arow] = av.z;
        As[acol + 3][arow] = av.w;
        float4 bv = *reinterpret_cast<const float4*>(B + (size_t)(k0 + brow) * N + bn + bcol);
        *reinterpret_cast<float4*>(&Bs[brow][bcol]) = bv;
        __syncthreads();
        #pragma unroll
        for (int kk = 0; kk < BKK; kk++) {
            float4 a4 = *reinterpret_cast<const float4*>(&As[kk][ty * 4]);
            float4 b4 = *reinterpret_cast<const float4*>(&Bs[kk][tx * 4]);
            float a[4] = {a4.x, a4.y, a4.z, a4.w};
            float b[4] = {b4.x, b4.y, b4.z, b4.w};
            #pragma unroll
            for (int i = 0; i < 4; i++)
                #pragma unroll
                for (int j = 0; j < 4; j++)
                    acc[i][j] += a[i] * b[j];
        }
        __syncthreads();
    }

    #pragma unroll
    for (int i = 0; i < 4; i++) {
        int m = bm + ty * 4 + i;
        if (m >= M) continue;
        #pragma unroll
        for (int j = 0; j < 4; j++) {
            int n = bn + tx * 4 + j;
            C[(size_t)m * N + n] = acc[i][j];
        }
    }
}

// ---------------- self-attention: flash, register softmax ----------------
// block = 128 queries x 1 head, 8 warps; warp owns rows [w*16, w*16+16)
__global__ __launch_bounds__(256, 2)
void attn_self_tc_kernel(const float* __restrict__ q, const float* __restrict__ k,
                         const float* __restrict__ v, float* __restrict__ o)
{
    __shared__ float Ks[64][44];
    __shared__ float Vs[64][44];
    __shared__ float Ps[8][16][68];

    const int h = blockIdx.y;
    const int q0 = blockIdx.x * 128;
    const int tid = threadIdx.x;
    const int warp = tid >> 5, lane = tid & 31;
    const int gid = lane >> 2, tig = lane & 3;

    // Q fragments (scaled), 5 k-steps of 8
    uint32_t qf[5][4];
    {
        const float* qp0 = q + (size_t)(q0 + warp * 16 + gid) * D_INNER + h * 40;
        const float* qp1 = qp0 + 8 * D_INNER;
        #pragma unroll
        for (int ks = 0; ks < 5; ks++) {
            qf[ks][0] = __float_as_uint(qp0[ks * 8 + tig] * ATT_SCALE);
            qf[ks][1] = __float_as_uint(qp1[ks * 8 + tig] * ATT_SCALE);
            qf[ks][2] = __float_as_uint(qp0[ks * 8 + tig + 4] * ATT_SCALE);
            qf[ks][3] = __float_as_uint(qp1[ks * 8 + tig + 4] * ATT_SCALE);
        }
    }

    float oacc[5][4];
    #pragma unroll
    for (int nt = 0; nt < 5; nt++)
        #pragma unroll
        for (int t = 0; t < 4; t++) oacc[nt][t] = 0.f;
    float m0 = -1e30f, m1 = -1e30f, l0 = 0.f, l1 = 0.f;

    for (int t0 = 0; t0 < S_TOK; t0 += 64) {
        __syncthreads();            // Ks/Vs free
        for (int i = tid; i < 640; i += 256) {
            int row = i / 10;
            int c4 = (i - row * 10) * 4;
            size_t gi = (size_t)(t0 + row) * D_INNER + h * 40 + c4;
            *reinterpret_cast<float4*>(&Ks[row][c4]) = *reinterpret_cast<const float4*>(k + gi);
            *reinterpret_cast<float4*>(&Vs[row][c4]) = *reinterpret_cast<const float4*>(v + gi);
        }
        __syncthreads();

        // S = Q @ K^T  (16 rows x 64 cols per warp)
        float sc[8][4];
        #pragma unroll
        for (int nt = 0; nt < 8; nt++) {
            sc[nt][0] = sc[nt][1] = sc[nt][2] = sc[nt][3] = 0.f;
            #pragma unroll
            for (int ks = 0; ks < 5; ks++) {
                uint32_t bf[2];
                bf[0] = __float_as_uint(Ks[nt * 8 + gid][ks * 8 + tig]);
                bf[1] = __float_as_uint(Ks[nt * 8 + gid][ks * 8 + tig + 4]);
                MMA_TF32(sc[nt], qf[ks], bf);
            }
        }

        // row max in registers (rows gid, gid+8 of this warp)
        float t0m = -1e30f, t1m = -1e30f;
        #pragma unroll
        for (int nt = 0; nt < 8; nt++) {
            t0m = fmaxf(t0m, fmaxf(sc[nt][0], sc[nt][1]));
            t1m = fmaxf(t1m, fmaxf(sc[nt][2], sc[nt][3]));
        }
        t0m = fmaxf(t0m, __shfl_xor_sync(0xffffffffu, t0m, 1));
        t0m = fmaxf(t0m, __shfl_xor_sync(0xffffffffu, t0m, 2));
        t1m = fmaxf(t1m, __shfl_xor_sync(0xffffffffu, t1m, 1));
        t1m = fmaxf(t1m, __shfl_xor_sync(0xffffffffu, t1m, 2));

        float mn0 = fmaxf(m0, t0m), mn1 = fmaxf(m1, t1m);
        float corr0 = __expf(m0 - mn0), corr1 = __expf(m1 - mn1);
        float sum0 = 0.f, sum1 = 0.f;
        #pragma unroll
        for (int nt = 0; nt < 8; nt++) {
            float p00 = to_tf32(__expf(sc[nt][0] - mn0));
            float p01 = to_tf32(__expf(sc[nt][1] - mn0));
            float p10 = to_tf32(__expf(sc[nt][2] - mn1));
            float p11 = to_tf32(__expf(sc[nt][3] - mn1));
            sum0 += p00 + p01;
            sum1 += p10 + p11;
            Ps[warp][gid][nt * 8 + tig * 2]         = p00;
            Ps[warp][gid][nt * 8 + tig * 2 + 1]     = p01;
            Ps[warp][gid + 8][nt * 8 + tig * 2]     = p10;
            Ps[warp][gid + 8][nt * 8 + tig * 2 + 1] = p11;
        }
        sum0 += __shfl_xor_sync(0xffffffffu, sum0, 1);
        sum0 += __shfl_xor_sync(0xffffffffu, sum0, 2);
        sum1 += __shfl_xor_sync(0xffffffffu, sum1, 1);
        sum1 += __shfl_xor_sync(0xffffffffu, sum1, 2);
        l0 = l0 * corr0 + sum0;
        l1 = l1 * corr1 + sum1;
        m0 = mn0; m1 = mn1;

        #pragma unroll
        for (int nt = 0; nt < 5; nt++) {
            oacc[nt][0] *= corr0; oacc[nt][1] *= corr0;
            oacc[nt][2] *= corr1; oacc[nt][3] *= corr1;
        }
        __syncwarp();

        // O += P @ V   (warp-private P)
        #pragma unroll
        for (int ks = 0; ks < 8; ks++) {
            uint32_t af[4];
            af[0] = __float_as_uint(Ps[warp][gid][ks * 8 + tig]);
            af[1] = __float_as_uint(Ps[warp][gid + 8][ks * 8 + tig]);
            af[2] = __float_as_uint(Ps[warp][gid][ks * 8 + tig + 4]);
            af[3] = __float_as_uint(Ps[warp][gid + 8][ks * 8 + tig + 4]);
            #pragma unroll
            for (int nt = 0; nt < 5; nt++) {
                uint32_t bf[2];
                bf[0] = __float_as_uint(Vs[ks * 8 + tig][nt * 8 + gid]);
                bf[1] = __float_as_uint(Vs[ks * 8 + tig + 4][nt * 8 + gid]);
                MMA_TF32(oacc[nt], af, bf);
            }
        }
    }

    float inv0 = 1.f / l0, inv1 = 1.f / l1;
    size_t base0 = (size_t)(q0 + warp * 16 + gid) * D_INNER + h * 40;
    size_t base1 = base0 + 8 * D_INNER;
    #pragma unroll
    for (int nt = 0; nt < 5; nt++) {
        int col = nt * 8 + tig * 2;
        o[base0 + col]     = oacc[nt][0] * inv0;
        o[base0 + col + 1] = oacc[nt][1] * inv0;
        o[base1 + col]     = oacc[nt][2] * inv1;
        o[base1 + col + 1] = oacc[nt][3] * inv1;
    }
}

// ---------------- cross-attention (77 keys, fp32) ----------------
__global__ __launch_bounds__(128)
void attn_cross_kernel(const float* __restrict__ q, const float* __restrict__ k2,
                       const float* __restrict__ v2, float* __restrict__ o)
{
    __shared__ float Ks[CTX_LEN * 40];
    __shared__ float Vs[CTX_LEN * 40];
    const int h  = blockIdx.y;
    const int q0 = blockIdx.x * 128;
    const int tid = threadIdx.x;

    for (int idx = tid; idx < CTX_LEN * 40; idx += 128) {
        int r = idx / 40;
        int d = idx - r * 40;
        Ks[idx] = k2[r * D_INNER + h * 40 + d];
        Vs[idx] = v2[r * D_INNER + h * 40 + d];
    }
    __syncthreads();

    float qr[40];
    #pragma unroll
    for (int d = 0; d < 40; d++)
        qr[d] = q[(size_t)(q0 + tid) * D_INNER + h * 40 + d] * ATT_SCALE;

    float m = -1e30f;
    for (int j = 0; j < CTX_LEN; j++) {
        float s = 0.f;
        #pragma unroll
        for (int d = 0; d < 40; d++) s += qr[d] * Ks[j * 40 + d];
        m = fmaxf(m, s);
    }
    float l = 0.f;
    float accv[40];
    #pragma unroll
    for (int d = 0; d < 40; d++) accv[d] = 0.f;
    for (int j = 0; j < CTX_LEN; j++) {
        float s = 0.f;
        #pragma unroll
        for (int d = 0; d < 40; d++) s += qr[d] * Ks[j * 40 + d];
        float p = __expf(s - m);
        l += p;
        #pragma unroll
        for (int d = 0; d < 40; d++) accv[d] += p * Vs[j * 40 + d];
    }
    float inv = 1.f / l;
    #pragma unroll
    for (int d = 0; d < 40; d++)
        o[(size_t)(q0 + tid) * D_INNER + h * 40 + d] = accv[d] * inv;
}

// ---------------- GEGLU ----------------
__global__ void geglu_kernel(const float* __restrict__ y, float* __restrict__ act)
{
    int idx = blockIdx.x * 256 + threadIdx.x;
    if (idx >= S_TOK * FF_HALF) return;
    int mrow = idx / FF_HALF;
    int j = idx - mrow * FF_HALF;
    float a = y[(size_t)mrow * FF_IN + j];
    float g = y[(size_t)mrow * FF_IN + FF_HALF + j];
    float ge = 0.5f * g * (1.f + erff(g * 0.70710678118654752f));
    act[idx] = a * ge;
}

// ---------------- host ----------------
static inline void gemm_tc(const float* A, const float* B, const float* bias,
                           const float* resid, float* C, int M, int N, int K, int flags)
{
    dim3 grid(N / GBN, M / GBM);
    gemm_tf32_kernel<<<grid, 128>>>(A, B, bias, resid, C, M, N, K, flags);
}

extern "C" void kernel_launch(void* const* d_in, const int* in_sizes, int n_in,
                              void* d_out, int out_size)
{
    const float* x          = (const float*)d_in[0];
    const float* context    = (const float*)d_in[1];
    const float* gn_scale   = (const float*)d_in[2];
    const float* gn_bias    = (const float*)d_in[3];
    const float* w_proj_in  = (const float*)d_in[4];
    const float* b_proj_in  = (const float*)d_in[5];
    const float* ln1_s      = (const float*)d_in[6];
    const float* ln1_b      = (const float*)d_in[7];
    const float* wq1        = (const float*)d_in[8];
    const float* wk1        = (const float*)d_in[9];
    const float* wv1        = (const float*)d_in[10];
    const float* wo1        = (const float*)d_in[11];
    const float* bo1        = (const float*)d_in[12];
    const float* ln2_s      = (const float*)d_in[13];
    const float* ln2_b      = (const float*)d_in[14];
    const float* wq2        = (const float*)d_in[15];
    const float* wk2        = (const float*)d_in[16];
    const float* wv2        = (const float*)d_in[17];
    const float* wo2        = (const float*)d_in[18];
    const float* bo2        = (const float*)d_in[19];
    const float* ln3_s      = (const float*)d_in[20];
    const float* ln3_b      = (const float*)d_in[21];
    const float* w_ff1      = (const float*)d_in[22];
    const float* b_ff1      = (const float*)d_in[23];
    const float* w_ff2      = (const float*)d_in[24];
    const float* b_ff2      = (const float*)d_in[25];
    const float* w_proj_out = (const float*)d_in[26];
    const float* b_proj_out = (const float*)d_in[27];
    float* out = (float*)d_out;

    float *gn, *h, *hn, *q, *k, *v, *attn, *ff, *act, *k2, *v2;
    cudaGetSymbolAddress((void**)&gn,   g_gn);
    cudaGetSymbolAddress((void**)&h,    g_h);
    cudaGetSymbolAddress((void**)&hn,   g_hn);
    cudaGetSymbolAddress((void**)&q,    g_q);
    cudaGetSymbolAddress((void**)&k,    g_k);
    cudaGetSymbolAddress((void**)&v,    g_v);
    cudaGetSymbolAddress((void**)&attn, g_attn);
    cudaGetSymbolAddress((void**)&ff,   g_ff);
    cudaGetSymbolAddress((void**)&act,  g_act);
    cudaGetSymbolAddress((void**)&k2,   g_k2);
    cudaGetSymbolAddress((void**)&v2,   g_v2);

    groupnorm_kernel<<<32, 256>>>(x, gn_scale, gn_bias, gn);
    gemm_tc(gn, w_proj_in, b_proj_in, nullptr, h, S_TOK, D_INNER, D_INNER, 0);

    // --- self attention ---
    layernorm_kernel<<<S_TOK / 8, 256>>>(h, ln1_s, ln1_b, hn);
    {
        dim3 grid(D_INNER / GBN, S_TOK / GBM, 3);
        gemm_qkv_kernel<<<grid, 128>>>(hn, wq1, wk1, wv1, q, k, v,
                                       S_TOK, D_INNER, D_INNER);
    }
    attn_self_tc_kernel<<<dim3(S_TOK / 128, HEADS), 256>>>(q, k, v, attn);
    gemm_tc(attn, wo1, bo1, h, h, S_TOK, D_INNER, D_INNER, 0);

    // --- cross attention ---
    layernorm_kernel<<<S_TOK / 8, 256>>>(h, ln2_s, ln2_b, hn);
    gemm_tc(hn, wq2, nullptr, nullptr, q, S_TOK, D_INNER, D_INNER, 0);
    sgemm_kernel<<<dim3(D_INNER / BN, 2), 256>>>(context, wk2, k2, CTX_LEN, D_INNER, CTX_DIM);
    sgemm_kernel<<<dim3(D_INNER / BN, 2), 256>>>(context, wv2, v2, CTX_LEN, D_INNER, CTX_DIM);
    attn_cross_kernel<<<dim3(S_TOK / 128, HEADS), 128>>>(q, k2, v2, attn);
    gemm_tc(attn, wo2, bo2, h, h, S_TOK, D_INNER, D_INNER, 0);

    // --- GEGLU feed forward ---
    layernorm_kernel<<<S_TOK / 8, 256>>>(h, ln3_s, ln3_b, hn);
    gemm_tc(hn, w_ff1, b_ff1, nullptr, ff, S_TOK, FF_IN, D_INNER, 0);
    geglu_kernel<<<(S_TOK * FF_HALF + 255) / 256, 256>>>(ff, act);
    gemm_tc(act, w_ff2, b_ff2, h, h, S_TOK, D_INNER, FF_HALF, 0);

    // --- proj_out (transposed store) + input residual ---
    gemm_tc(h, w_proj_out, b_proj_out, x, out, S_TOK, D_INNER, D_INNER, 1);
}

// round 5
// speedup vs baseline: 3.4680x; 1.2891x over previous
#include <cuda_runtime.h>
#include <math.h>
#include <stdint.h>

#define S_TOK   4096
#define D_INNER 320
#define HEADS   8
#define DHEAD   40
#define CTX_LEN 77
#define CTX_DIM 768
#define FF_IN   2560
#define FF_HALF 1280
#define ATT_SCALE 0.15811388300841897f

// ---------------- scratch ----------------
__device__ float g_gn  [S_TOK * D_INNER];
__device__ float g_h   [S_TOK * D_INNER];
__device__ float g_hn  [S_TOK * D_INNER];
__device__ float g_q   [S_TOK * D_INNER];
__device__ float g_k   [S_TOK * D_INNER];
__device__ float g_v   [S_TOK * D_INNER];
__device__ float g_attn[S_TOK * D_INNER];
__device__ float g_ff  [S_TOK * FF_IN];
__device__ float g_act [S_TOK * FF_HALF];
__device__ float g_k2  [CTX_LEN * D_INNER];
__device__ float g_v2  [CTX_LEN * D_INNER];
__device__ float g_wT  [2539520];     // all weights transposed to [n][k]

#define MMA_TF32(c, a, b) \
    asm volatile("mma.sync.aligned.m16n8k8.row.col.f32.tf32.tf32.f32 " \
                 "{%0,%1,%2,%3},{%4,%5,%6,%7},{%8,%9},{%0,%1,%2,%3};" \
                 : "+f"((c)[0]), "+f"((c)[1]), "+f"((c)[2]), "+f"((c)[3]) \
                 : "r"((a)[0]), "r"((a)[1]), "r"((a)[2]), "r"((a)[3]), \
                   "r"((b)[0]), "r"((b)[1]))

#define LDMX4(r0, r1, r2, r3, addr) \
    asm volatile("ldmatrix.sync.aligned.m8n8.x4.shared.b16 {%0,%1,%2,%3}, [%4];" \
                 : "=r"(r0), "=r"(r1), "=r"(r2), "=r"(r3) : "r"(addr))

__device__ __forceinline__ void cp_async16(uint32_t s, const void* g) {
    asm volatile("cp.async.cg.shared.global [%0], [%1], 16;" :: "r"(s), "l"(g));
}
__device__ __forceinline__ void cp_commit() {
    asm volatile("cp.async.commit_group;");
}
template<int W> __device__ __forceinline__ void cp_wait() {
    asm volatile("cp.async.wait_group %0;" :: "n"(W));
}
__device__ __forceinline__ uint32_t smem_u32(const void* p) {
    return (uint32_t)__cvta_generic_to_shared(p);
}

// ---------------- weight transpose (batched) ----------------
struct TDesc { const float* src; float* dst; int K; int N; };
struct TArgs { TDesc d[12]; };

__global__ void transpose_all_kernel(TArgs a)
{
    TDesc t = a.d[blockIdx.z];
    __shared__ float tile[32][33];
    int tx = threadIdx.x, ty = threadIdx.y;
    int x = blockIdx.x * 32 + tx;
    int y0 = blockIdx.y * 32;
    if (blockIdx.x * 32 >= t.N || y0 >= t.K) return;
    #pragma unroll
    for (int j = 0; j < 4; j++) {
        int y = y0 + ty + j * 8;
        if (y < t.K && x < t.N)
            tile[ty + j * 8][tx] = t.src[(size_t)y * t.N + x];
    }
    __syncthreads();
    int x2 = blockIdx.y * 32 + tx;
    int y20 = blockIdx.x * 32;
    #pragma unroll
    for (int j = 0; j < 4; j++) {
        int y2 = y20 + ty + j * 8;
        if (y2 < t.N && x2 < t.K)
            t.dst[(size_t)y2 * t.K + x2] = tile[tx][ty + j * 8];
    }
}

// ---------------- GroupNorm + transpose to [s,c] ----------------
__global__ void groupnorm_kernel(const float* __restrict__ x,
                                 const float* __restrict__ scale,
                                 const float* __restrict__ bias,
                                 float* __restrict__ outT)
{
    const int g = blockIdx.x;
    const int c0 = g * 10;
    const int N = 10 * S_TOK;
    __shared__ float ssum[1024], ssq[1024];
    float s = 0.f, sq = 0.f;
    for (int i = threadIdx.x; i < N; i += 1024) {
        float v = x[c0 * S_TOK + i];
        s += v; sq += v * v;
    }
    ssum[threadIdx.x] = s; ssq[threadIdx.x] = sq;
    __syncthreads();
    for (int off = 512; off > 0; off >>= 1) {
        if (threadIdx.x < off) {
            ssum[threadIdx.x] += ssum[threadIdx.x + off];
            ssq[threadIdx.x]  += ssq[threadIdx.x + off];
        }
        __syncthreads();
    }
    __shared__ float smean, srstd;
    if (threadIdx.x == 0) {
        float mean = ssum[0] / (float)N;
        float var  = ssq[0] / (float)N - mean * mean;
        smean = mean;
        srstd = rsqrtf(var + 1e-6f);
    }
    __syncthreads();
    float mean = smean, rstd = srstd;
    for (int i = threadIdx.x; i < N; i += 1024) {
        int c = c0 + i / S_TOK;
        int sp = i - (i / S_TOK) * S_TOK;
        float v = (x[c0 * S_TOK + i] - mean) * rstd * scale[c] + bias[c];
        outT[sp * D_INNER + c] = v;
    }
}

// ---------------- LayerNorm ----------------
__global__ void layernorm_kernel(const float* __restrict__ in,
                                 const float* __restrict__ s,
                                 const float* __restrict__ b,
                                 float* __restrict__ out)
{
    int row = blockIdx.x * 8 + (threadIdx.x >> 5);
    int lane = threadIdx.x & 31;
    const float* xr = in + row * D_INNER;
    float sum = 0.f, sq = 0.f;
    for (int i = lane; i < D_INNER; i += 32) {
        float v = xr[i];
        sum += v; sq += v * v;
    }
    #pragma unroll
    for (int off = 16; off > 0; off >>= 1) {
        sum += __shfl_xor_sync(0xffffffffu, sum, off);
        sq  += __shfl_xor_sync(0xffffffffu, sq,  off);
    }
    float mean = sum / (float)D_INNER;
    float var  = sq / (float)D_INNER - mean * mean;
    float rstd = rsqrtf(var + 1e-5f);
    for (int i = lane; i < D_INNER; i += 32)
        out[row * D_INNER + i] = (xr[i] - mean) * rstd * s[i] + b[i];
}

// ---------------- tf32 GEMM: 64x64x32, 128 thr, 3-stage cp.async, ldmatrix ----
// A [M][K] row-major; BT [N][K] (pre-transposed weights)
#define GBM 64
#define GBN 64
#define GBK 32
#define GEMM_SMEM_BYTES (6 * 2304 * 4)   // 3 stages x (As 64x36 + Bs 64x36)

__device__ __forceinline__ void gemm_core(
    const float* __restrict__ A, const float* __restrict__ BT,
    const float* __restrict__ bias, const float* __restrict__ resid,
    float* __restrict__ C, int M, int N, int K, int flags, int bm, int bn)
{
    extern __shared__ float sm[];
    const int tid = threadIdx.x;
    const int warp = tid >> 5, lane = tid & 31;
    const int wm = (warp >> 1) * 32, wn = (warp & 1) * 32;
    const int gid = lane >> 2, tig = lane & 3;

    float c[2][4][4];
    #pragma unroll
    for (int i = 0; i < 2; i++)
        #pragma unroll
        for (int j = 0; j < 4; j++)
            #pragma unroll
            for (int t = 0; t < 4; t++) c[i][j][t] = 0.f;

    const int nk = K / GBK;

    const int lr = tid >> 3;
    const int lc = (tid & 7) * 4;

    auto load_stage = [&](int s, int k0) {
        #pragma unroll
        for (int i = 0; i < 4; i++) {
            int r = lr + i * 16;
            cp_async16(smem_u32(&sm[s * 2304 + r * 36 + lc]),
                       A + (size_t)(bm + r) * K + k0 + lc);
        }
        #pragma unroll
        for (int i = 0; i < 4; i++) {
            int r = lr + i * 16;
            cp_async16(smem_u32(&sm[6912 + s * 2304 + r * 36 + lc]),
                       BT + (size_t)(bn + r) * K + k0 + lc);
        }
    };

    load_stage(0, 0); cp_commit();
    load_stage(1, GBK); cp_commit();

    const int a_row = wm + (lane & 15);
    const int a_col = (lane >> 4) * 4;
    const int b_row = wn + (lane & 7) + ((lane >> 4) << 3);
    const int b_col = ((lane >> 3) & 1) * 4;

    for (int t = 0; t < nk; t++) {
        cp_wait<1>();
        __syncthreads();
        if (t + 2 < nk) load_stage((t + 2) % 3, (t + 2) * GBK);
        cp_commit();

        const int s = t % 3;
        float* as = &sm[s * 2304];
        float* bs = &sm[6912 + s * 2304];

        #pragma unroll
        for (int ks = 0; ks < GBK; ks += 8) {
            uint32_t af[2][4], bf[4][2];
            #pragma unroll
            for (int mt = 0; mt < 2; mt++) {
                uint32_t addr = smem_u32(&as[(a_row + mt * 16) * 36 + ks + a_col]);
                LDMX4(af[mt][0], af[mt][1], af[mt][2], af[mt][3], addr);
            }
            #pragma unroll
            for (int p = 0; p < 2; p++) {
                uint32_t addr = smem_u32(&bs[(b_row + p * 16) * 36 + ks + b_col]);
                LDMX4(bf[2 * p][0], bf[2 * p][1], bf[2 * p + 1][0], bf[2 * p + 1][1], addr);
            }
            #pragma unroll
            for (int mt = 0; mt < 2; mt++)
                #pragma unroll
                for (int nt = 0; nt < 4; nt++)
                    MMA_TF32(c[mt][nt], af[mt], bf[nt]);
        }
        __syncthreads();
    }

    #pragma unroll
    for (int mt = 0; mt < 2; mt++) {
        int r0 = bm + wm + mt * 16 + gid;
        int r1 = r0 + 8;
        #pragma unroll
        for (int nt = 0; nt < 4; nt++) {
            int col = bn + wn + nt * 8 + tig * 2;
            float v00 = c[mt][nt][0], v01 = c[mt][nt][1];
            float v10 = c[mt][nt][2], v11 = c[mt][nt][3];
            if (bias) {
                float b0 = bias[col], b1 = bias[col + 1];
                v00 += b0; v01 += b1; v10 += b0; v11 += b1;
            }
            if (!(flags & 1)) {
                if (resid) {
                    v00 += resid[(size_t)r0 * N + col];
                    v01 += resid[(size_t)r0 * N + col + 1];
                    v10 += resid[(size_t)r1 * N + col];
                    v11 += resid[(size_t)r1 * N + col + 1];
                }
                C[(size_t)r0 * N + col]     = v00;
                C[(size_t)r0 * N + col + 1] = v01;
                C[(size_t)r1 * N + col]     = v10;
                C[(size_t)r1 * N + col + 1] = v11;
            } else {
                if (resid) {
                    v00 += resid[(size_t)col * M + r0];
                    v01 += resid[(size_t)(col + 1) * M + r0];
                    v10 += resid[(size_t)col * M + r1];
                    v11 += resid[(size_t)(col + 1) * M + r1];
                }
                C[(size_t)col * M + r0]       = v00;
                C[(size_t)(col + 1) * M + r0] = v01;
                C[(size_t)col * M + r1]       = v10;
                C[(size_t)(col + 1) * M + r1] = v11;
            }
        }
    }
}

__global__ __launch_bounds__(128)
void gemm_tf32_kernel(const float* __restrict__ A, const float* __restrict__ BT,
                      const float* __restrict__ bias, const float* __restrict__ resid,
                      float* __restrict__ C, int M, int N, int K, int flags)
{
    gemm_core(A, BT, bias, resid, C, M, N, K, flags,
              blockIdx.y * GBM, blockIdx.x * GBN);
}

__global__ __launch_bounds__(128)
void gemm_qkv_kernel(const float* __restrict__ A,
                     const float* __restrict__ B0, const float* __restrict__ B1,
                     const float* __restrict__ B2,
                     float* __restrict__ C0, float* __restrict__ C1,
                     float* __restrict__ C2, int M, int N, int K)
{
    const float* B = (blockIdx.z == 0) ? B0 : (blockIdx.z == 1) ? B1 : B2;
    float* C       = (blockIdx.z == 0) ? C0 : (blockIdx.z == 1) ? C1 : C2;
    gemm_core(A, B, nullptr, nullptr, C, M, N, K, 0,
              blockIdx.y * GBM, blockIdx.x * GBN);
}

// ---------------- fp32 SGEMM for small M (ctx K/V, grid.z selects) ----------
// FIX R5: restored M-tiling via blockIdx.y (M=77 needs 2 row-tiles of 64)
#define BM 64
#define BN 64
#define BKK 16
__global__ __launch_bounds__(256)
void sgemm_ctx_kernel(const float* __restrict__ A,
                      const float* __restrict__ B0, const float* __restrict__ B1,
                      float* __restrict__ C0, float* __restrict__ C1,
                      int M, int N, int K)
{
    const float* B = (blockIdx.z == 0) ? B0 : B1;
    float* C       = (blockIdx.z == 0) ? C0 : C1;
    __shared__ float As[BKK][BM];
    __shared__ float Bs[BKK][BN];
    const int bm = blockIdx.y * BM;
    const int bn = blockIdx.x * BN;
    const int tid = threadIdx.x;
    const int tx = tid & 15;
    const int ty = tid >> 4;
    const int arow = tid >> 2;
    const int acol = (tid & 3) * 4;
    const int brow = tid >> 4;
    const int bcol = (tid & 15) * 4;

    float acc[4][4];
    #pragma unroll
    for (int i = 0; i < 4; i++)
        #pragma unroll
        for (int j = 0; j < 4; j++) acc[i][j] = 0.f;

    for (int k0 = 0; k0 < K; k0 += BKK) {
        float4 av = make_float4(0.f, 0.f, 0.f, 0.f);
        if (bm + arow < M)
            av = *reinterpret_cast<const float4*>(A + (size_t)(bm + arow) * K + k0 + acol);
        As[acol + 0][arow] = av.x;
        As[acol + 1][arow] = av.y;
        As[acol + 2][arow] = av.z;
        As[acol + 3][arow] = av.w;
        float4 bv = *reinterpret_cast<const float4*>(B + (size_t)(k0 + brow) * N + bn + bcol);
        *reinterpret_cast<float4*>(&Bs[brow][bcol]) = bv;
        __syncthreads();
        #pragma unroll
        for (int kk = 0; kk < BKK; kk++) {
            float4 a4 = *reinterpret_cast<const float4*>(&As[kk][ty * 4]);
            float4 b4 = *reinterpret_cast<const float4*>(&Bs[kk][tx * 4]);
            float a[4] = {a4.x, a4.y, a4.z, a4.w};
            float b[4] = {b4.x, b4.y, b4.z, b4.w};
            #pragma unroll
            for (int i = 0; i < 4; i++)
                #pragma unroll
                for (int j = 0; j < 4; j++)
                    acc[i][j] += a[i] * b[j];
        }
        __syncthreads();
    }

    #pragma unroll
    for (int i = 0; i < 4; i++) {
        int m = bm + ty * 4 + i;
        if (m >= M) continue;
        #pragma unroll
        for (int j = 0; j < 4; j++)
            C[(size_t)m * N + bn + tx * 4 + j] = acc[i][j];
    }
}

// ---------------- self-attention: flash tf32, ldmatrix, cp.async 2-buffer -----
// block = 128 queries x 1 head, 8 warps
// dyn smem: Ks[2][64][44] | Vs[2][64][40] | Ps[8][16][68]
#define ATTN_SMEM_BYTES ((2*64*44 + 2*64*40 + 8*16*68) * 4)

__global__ __launch_bounds__(256, 2)
void attn_self_tc_kernel(const float* __restrict__ q, const float* __restrict__ k,
                         const float* __restrict__ v, float* __restrict__ o)
{
    extern __shared__ float sm[];
    float* Ksb = sm;                         // [2][64][44]
    float* Vsb = sm + 2 * 64 * 44;           // [2][64][40]
    float* Psb = Vsb + 2 * 64 * 40;          // [8][16][68]

    const int h = blockIdx.y;
    const int q0 = blockIdx.x * 128;
    const int tid = threadIdx.x;
    const int warp = tid >> 5, lane = tid & 31;
    const int gid = lane >> 2, tig = lane & 3;

    uint32_t qf[5][4];
    {
        const float* qp0 = q + (size_t)(q0 + warp * 16 + gid) * D_INNER + h * 40;
        const float* qp1 = qp0 + 8 * D_INNER;
        #pragma unroll
        for (int ks = 0; ks < 5; ks++) {
            qf[ks][0] = __float_as_uint(qp0[ks * 8 + tig] * ATT_SCALE);
            qf[ks][1] = __float_as_uint(qp1[ks * 8 + tig] * ATT_SCALE);
            qf[ks][2] = __float_as_uint(qp0[ks * 8 + tig + 4] * ATT_SCALE);
            qf[ks][3] = __float_as_uint(qp1[ks * 8 + tig + 4] * ATT_SCALE);
        }
    }

    float oacc[5][4];
    #pragma unroll
    for (int nt = 0; nt < 5; nt++)
        #pragma unroll
        for (int t = 0; t < 4; t++) oacc[nt][t] = 0.f;
    float m0 = -1e30f, m1 = -1e30f, l0 = 0.f, l1 = 0.f;

    auto load_tile = [&](int buf, int t0) {
        #pragma unroll
        for (int j = 0; j < 3; j++) {
            int i = tid + j * 256;
            if (i < 640) {
                int row = i / 10;
                int c4 = (i - row * 10) * 4;
                size_t gi = (size_t)(t0 + row) * D_INNER + h * 40 + c4;
                cp_async16(smem_u32(&Ksb[buf * 2816 + row * 44 + c4]), k + gi);
                cp_async16(smem_u32(&Vsb[buf * 2560 + row * 40 + c4]), v + gi);
            }
        }
    };

    load_tile(0, 0); cp_commit();

    float* Pw = &Psb[warp * 1088];   // [16][68]
    const uint32_t p_ld_addr = smem_u32(&Pw[(lane & 15) * 68 + ((lane >> 4) * 4)]);

    const int NTILES = S_TOK / 64;
    for (int t = 0; t < NTILES; t++) {
        __syncthreads();
        if (t + 1 < NTILES) load_tile((t + 1) & 1, (t + 1) * 64);
        cp_commit();
        cp_wait<1>();
        __syncthreads();

        const float* ks_ = &Ksb[(t & 1) * 2816];
        const float* vs_ = &Vsb[(t & 1) * 2560];

        // ---- S = Q @ K^T ----
        float sc[8][4];
        const int k_row = (lane & 7) + ((lane >> 4) << 3);
        const int k_col = ((lane >> 3) & 1) * 4;
        #pragma unroll
        for (int p = 0; p < 4; p++)
            #pragma unroll
            for (int tt = 0; tt < 2; tt++)
                #pragma unroll
                for (int e = 0; e < 4; e++) sc[2 * p + tt][e] = 0.f;
        #pragma unroll
        for (int ks = 0; ks < 5; ks++) {
            #pragma unroll
            for (int p = 0; p < 4; p++) {
                uint32_t r0, r1, r2, r3;
                uint32_t addr = smem_u32(&ks_[(p * 16 + k_row) * 44 + ks * 8 + k_col]);
                LDMX4(r0, r1, r2, r3, addr);
                uint32_t b0[2] = {r0, r1}, b1[2] = {r2, r3};
                MMA_TF32(sc[2 * p],     qf[ks], b0);
                MMA_TF32(sc[2 * p + 1], qf[ks], b1);
            }
        }

        // ---- online softmax (register) ----
        float t0m = -1e30f, t1m = -1e30f;
        #pragma unroll
        for (int nt = 0; nt < 8; nt++) {
            t0m = fmaxf(t0m, fmaxf(sc[nt][0], sc[nt][1]));
            t1m = fmaxf(t1m, fmaxf(sc[nt][2], sc[nt][3]));
        }
        t0m = fmaxf(t0m, __shfl_xor_sync(0xffffffffu, t0m, 1));
        t0m = fmaxf(t0m, __shfl_xor_sync(0xffffffffu, t0m, 2));
        t1m = fmaxf(t1m, __shfl_xor_sync(0xffffffffu, t1m, 1));
        t1m = fmaxf(t1m, __shfl_xor_sync(0xffffffffu, t1m, 2));

        float mn0 = fmaxf(m0, t0m), mn1 = fmaxf(m1, t1m);
        float corr0 = __expf(m0 - mn0), corr1 = __expf(m1 - mn1);
        float sum0 = 0.f, sum1 = 0.f;
        #pragma unroll
        for (int nt = 0; nt < 8; nt++) {
            float p00 = __expf(sc[nt][0] - mn0);
            float p01 = __expf(sc[nt][1] - mn0);
            float p10 = __expf(sc[nt][2] - mn1);
            float p11 = __expf(sc[nt][3] - mn1);
            sum0 += p00 + p01;
            sum1 += p10 + p11;
            *reinterpret_cast<float2*>(&Pw[gid * 68 + nt * 8 + tig * 2]) = make_float2(p00, p01);
            *reinterpret_cast<float2*>(&Pw[(gid + 8) * 68 + nt * 8 + tig * 2]) = make_float2(p10, p11);
        }
        sum0 += __shfl_xor_sync(0xffffffffu, sum0, 1);
        sum0 += __shfl_xor_sync(0xffffffffu, sum0, 2);
        sum1 += __shfl_xor_sync(0xffffffffu, sum1, 1);
        sum1 += __shfl_xor_sync(0xffffffffu, sum1, 2);
        l0 = l0 * corr0 + sum0;
        l1 = l1 * corr1 + sum1;
        m0 = mn0; m1 = mn1;

        #pragma unroll
        for (int nt = 0; nt < 5; nt++) {
            oacc[nt][0] *= corr0; oacc[nt][1] *= corr0;
            oacc[nt][2] *= corr1; oacc[nt][3] *= corr1;
        }
        __syncwarp();

        // ---- O += P @ V ----
        #pragma unroll
        for (int ks = 0; ks < 8; ks++) {
            uint32_t af[4];
            LDMX4(af[0], af[1], af[2], af[3], p_ld_addr + ks * 32);
            #pragma unroll
            for (int nt = 0; nt < 5; nt++) {
                uint32_t bf[2];
                bf[0] = __float_as_uint(vs_[(ks * 8 + tig) * 40 + nt * 8 + gid]);
                bf[1] = __float_as_uint(vs_[(ks * 8 + tig + 4) * 40 + nt * 8 + gid]);
                MMA_TF32(oacc[nt], af, bf);
            }
        }
    }

    float inv0 = 1.f / l0, inv1 = 1.f / l1;
    size_t base0 = (size_t)(q0 + warp * 16 + gid) * D_INNER + h * 40;
    size_t base1 = base0 + 8 * D_INNER;
    #pragma unroll
    for (int nt = 0; nt < 5; nt++) {
        int col = nt * 8 + tig * 2;
        o[base0 + col]     = oacc[nt][0] * inv0;
        o[base0 + col + 1] = oacc[nt][1] * inv0;
        o[base1 + col]     = oacc[nt][2] * inv1;
        o[base1 + col + 1] = oacc[nt][3] * inv1;
    }
}

// ---------------- cross-attention (77 keys, fp32) ----------------
__global__ __launch_bounds__(128)
void attn_cross_kernel(const float* __restrict__ q, const float* __restrict__ k2,
                       const float* __restrict__ v2, float* __restrict__ o)
{
    __shared__ float Ks[CTX_LEN * 40];
    __shared__ float Vs[CTX_LEN * 40];
    const int h  = blockIdx.y;
    const int q0 = blockIdx.x * 128;
    const int tid = threadIdx.x;

    for (int idx = tid; idx < CTX_LEN * 40; idx += 128) {
        int r = idx / 40;
        int d = idx - r * 40;
        Ks[idx] = k2[r * D_INNER + h * 40 + d];
        Vs[idx] = v2[r * D_INNER + h * 40 + d];
    }
    __syncthreads();

    float qr[40];
    #pragma unroll
    for (int d = 0; d < 40; d++)
        qr[d] = q[(size_t)(q0 + tid) * D_INNER + h * 40 + d] * ATT_SCALE;

    float m = -1e30f;
    for (int j = 0; j < CTX_LEN; j++) {
        float s = 0.f;
        #pragma unroll
        for (int d = 0; d < 40; d++) s += qr[d] * Ks[j * 40 + d];
        m = fmaxf(m, s);
    }
    float l = 0.f;
    float accv[40];
    #pragma unroll
    for (int d = 0; d < 40; d++) accv[d] = 0.f;
    for (int j = 0; j < CTX_LEN; j++) {
        float s = 0.f;
        #pragma unroll
        for (int d = 0; d < 40; d++) s += qr[d] * Ks[j * 40 + d];
        float p = __expf(s - m);
        l += p;
        #pragma unroll
        for (int d = 0; d < 40; d++) accv[d] += p * Vs[j * 40 + d];
    }
    float inv = 1.f / l;
    #pragma unroll
    for (int d = 0; d < 40; d++)
        o[(size_t)(q0 + tid) * D_INNER + h * 40 + d] = accv[d] * inv;
}

// ---------------- GEGLU ----------------
__global__ void geglu_kernel(const float* __restrict__ y, float* __restrict__ act)
{
    int idx = blockIdx.x * 256 + threadIdx.x;
    if (idx >= S_TOK * FF_HALF) return;
    int mrow = idx / FF_HALF;
    int j = idx - mrow * FF_HALF;
    float a = y[(size_t)mrow * FF_IN + j];
    float g = y[(size_t)mrow * FF_IN + FF_HALF + j];
    float ge = 0.5f * g * (1.f + erff(g * 0.70710678118654752f));
    act[idx] = a * ge;
}

// ---------------- host ----------------
static inline void gemm_tc(const float* A, const float* BT, const float* bias,
                           const float* resid, float* C, int M, int N, int K, int flags)
{
    dim3 grid(N / GBN, M / GBM);
    gemm_tf32_kernel<<<grid, 128, GEMM_SMEM_BYTES>>>(A, BT, bias, resid, C, M, N, K, flags);
}

extern "C" void kernel_launch(void* const* d_in, const int* in_sizes, int n_in,
                              void* d_out, int out_size)
{
    const float* x          = (const float*)d_in[0];
    const float* context    = (const float*)d_in[1];
    const float* gn_scale   = (const float*)d_in[2];
    const float* gn_bias    = (const float*)d_in[3];
    const float* w_proj_in  = (const float*)d_in[4];
    const float* b_proj_in  = (const float*)d_in[5];
    const float* ln1_s      = (const float*)d_in[6];
    const float* ln1_b      = (const float*)d_in[7];
    const float* wq1        = (const float*)d_in[8];
    const float* wk1        = (const float*)d_in[9];
    const float* wv1        = (const float*)d_in[10];
    const float* wo1        = (const float*)d_in[11];
    const float* bo1        = (const float*)d_in[12];
    const float* ln2_s      = (const float*)d_in[13];
    const float* ln2_b      = (const float*)d_in[14];
    const float* wq2        = (const float*)d_in[15];
    const float* wk2        = (const float*)d_in[16];
    const float* wv2        = (const float*)d_in[17];
    const float* wo2        = (const float*)d_in[18];
    const float* bo2        = (const float*)d_in[19];
    const float* ln3_s      = (const float*)d_in[20];
    const float* ln3_b      = (const float*)d_in[21];
    const float* w_ff1      = (const float*)d_in[22];
    const float* b_ff1      = (const float*)d_in[23];
    const float* w_ff2      = (const float*)d_in[24];
    const float* b_ff2      = (const float*)d_in[25];
    const float* w_proj_out = (const float*)d_in[26];
    const float* b_proj_out = (const float*)d_in[27];
    float* out = (float*)d_out;

    float *gn, *h, *hn, *q, *k, *v, *attn, *ff, *act, *k2, *v2, *wT;
    cudaGetSymbolAddress((void**)&gn,   g_gn);
    cudaGetSymbolAddress((void**)&h,    g_h);
    cudaGetSymbolAddress((void**)&hn,   g_hn);
    cudaGetSymbolAddress((void**)&q,    g_q);
    cudaGetSymbolAddress((void**)&k,    g_k);
    cudaGetSymbolAddress((void**)&v,    g_v);
    cudaGetSymbolAddress((void**)&attn, g_attn);
    cudaGetSymbolAddress((void**)&ff,   g_ff);
    cudaGetSymbolAddress((void**)&act,  g_act);
    cudaGetSymbolAddress((void**)&k2,   g_k2);
    cudaGetSymbolAddress((void**)&v2,   g_v2);
    cudaGetSymbolAddress((void**)&wT,   g_wT);

    static_assert(GEMM_SMEM_BYTES <= 227000, "");
    cudaFuncSetAttribute(gemm_tf32_kernel, cudaFuncAttributeMaxDynamicSharedMemorySize, GEMM_SMEM_BYTES);
    cudaFuncSetAttribute(gemm_qkv_kernel,  cudaFuncAttributeMaxDynamicSharedMemorySize, GEMM_SMEM_BYTES);
    cudaFuncSetAttribute(attn_self_tc_kernel, cudaFuncAttributeMaxDynamicSharedMemorySize, ATTN_SMEM_BYTES);

    float* t_proj_in  = wT + 0;
    float* t_wq1      = wT + 102400;
    float* t_wk1      = wT + 204800;
    float* t_wv1      = wT + 307200;
    float* t_wo1      = wT + 409600;
    float* t_wq2      = wT + 512000;
    float* t_wk2      = wT + 614400;
    float* t_wv2      = wT + 860160;
    float* t_wo2      = wT + 1105920;
    float* t_ff1      = wT + 1208320;
    float* t_ff2      = wT + 2027520;
    float* t_proj_out = wT + 2437120;

    TArgs ta;
    ta.d[0]  = {w_proj_in,  t_proj_in,  320,  320};
    ta.d[1]  = {wq1,        t_wq1,      320,  320};
    ta.d[2]  = {wk1,        t_wk1,      320,  320};
    ta.d[3]  = {wv1,        t_wv1,      320,  320};
    ta.d[4]  = {wo1,        t_wo1,      320,  320};
    ta.d[5]  = {wq2,        t_wq2,      320,  320};
    ta.d[6]  = {wk2,        t_wk2,      768,  320};
    ta.d[7]  = {wv2,        t_wv2,      768,  320};
    ta.d[8]  = {wo2,        t_wo2,      320,  320};
    ta.d[9]  = {w_ff1,      t_ff1,      320,  2560};
    ta.d[10] = {w_ff2,      t_ff2,      1280, 320};
    ta.d[11] = {w_proj_out, t_proj_out, 320,  320};
    transpose_all_kernel<<<dim3(80, 40, 12), dim3(32, 8)>>>(ta);

    groupnorm_kernel<<<32, 1024>>>(x, gn_scale, gn_bias, gn);
    gemm_tc(gn, t_proj_in, b_proj_in, nullptr, h, S_TOK, D_INNER, D_INNER, 0);

    // --- self attention ---
    layernorm_kernel<<<S_TOK / 8, 256>>>(h, ln1_s, ln1_b, hn);
    {
        dim3 grid(D_INNER / GBN, S_TOK / GBM, 3);
        gemm_qkv_kernel<<<grid, 128, GEMM_SMEM_BYTES>>>(hn, t_wq1, t_wk1, t_wv1,
                                                        q, k, v, S_TOK, D_INNER, D_INNER);
    }
    attn_self_tc_kernel<<<dim3(S_TOK / 128, HEADS), 256, ATTN_SMEM_BYTES>>>(q, k, v, attn);
    gemm_tc(attn, t_wo1, bo1, h, h, S_TOK, D_INNER, D_INNER, 0);

    // --- cross attention ---
    layernorm_kernel<<<S_TOK / 8, 256>>>(h, ln2_s, ln2_b, hn);
    gemm_tc(hn, t_wq2, nullptr, nullptr, q, S_TOK, D_INNER, D_INNER, 0);
    sgemm_ctx_kernel<<<dim3(D_INNER / BN, (CTX_LEN + BM - 1) / BM, 2), 256>>>(
        context, wk2, wv2, k2, v2, CTX_LEN, D_INNER, CTX_DIM);
    attn_cross_kernel<<<dim3(S_TOK / 128, HEADS), 128>>>(q, k2, v2, attn);
    gemm_tc(attn, t_wo2, bo2, h, h, S_TOK, D_INNER, D_INNER, 0);

    // --- GEGLU feed forward ---
    layernorm_kernel<<<S_TOK / 8, 256>>>(h, ln3_s, ln3_b, hn);
    gemm_tc(hn, t_ff1, b_ff1, nullptr, ff, S_TOK, FF_IN, D_INNER, 0);
    geglu_kernel<<<(S_TOK * FF_HALF + 255) / 256, 256>>>(ff, act);
    gemm_tc(act, t_ff2, b_ff2, h, h, S_TOK, D_INNER, FF_HALF, 0);

    // --- proj_out (transposed store) + input residual ---
    gemm_tc(h, t_proj_out, b_proj_out, x, out, S_TOK, D_INNER, D_INNER, 1);
}

// round 6
// speedup vs baseline: 4.0531x; 1.1687x over previous
#include <cuda_runtime.h>
#include <cuda_fp16.h>
#include <math.h>
#include <stdint.h>

#define S_TOK   4096
#define D_INNER 320
#define HEADS   8
#define DHEAD   40
#define CTX_LEN 77
#define CTX_DIM 768
#define FF_IN   2560
#define FF_HALF 1280
#define ATT_SCALE 0.15811388300841897f

// ---------------- scratch ----------------
__device__ float  g_h  [S_TOK * D_INNER];          // fp32 residual stream
__device__ float  g_ff [S_TOK * FF_IN];            // fp32 ff intermediate
__device__ __half g_hh [S_TOK * D_INNER];          // half copy of h (for proj_out)
__device__ __half g_gn [S_TOK * D_INNER];
__device__ __half g_hn [S_TOK * D_INNER];
__device__ __half g_q  [S_TOK * D_INNER];
__device__ __half g_k  [S_TOK * D_INNER];
__device__ __half g_v  [S_TOK * D_INNER];
__device__ __half g_at [S_TOK * D_INNER];
__device__ __half g_act[S_TOK * FF_HALF];
__device__ __half g_k2 [CTX_LEN * D_INNER];
__device__ __half g_v2 [CTX_LEN * D_INNER];
__device__ __half g_wTh[2539520];                  // all weights half, [n][k]

#define MMA_F16(c, a, b) \
    asm volatile("mma.sync.aligned.m16n8k16.row.col.f32.f16.f16.f32 " \
                 "{%0,%1,%2,%3},{%4,%5,%6,%7},{%8,%9},{%0,%1,%2,%3};" \
                 : "+f"((c)[0]), "+f"((c)[1]), "+f"((c)[2]), "+f"((c)[3]) \
                 : "r"((a)[0]), "r"((a)[1]), "r"((a)[2]), "r"((a)[3]), \
                   "r"((b)[0]), "r"((b)[1]))

#define MMA_F16_K8(c, a0, a1, b0) \
    asm volatile("mma.sync.aligned.m16n8k8.row.col.f32.f16.f16.f32 " \
                 "{%0,%1,%2,%3},{%4,%5},{%6},{%0,%1,%2,%3};" \
                 : "+f"((c)[0]), "+f"((c)[1]), "+f"((c)[2]), "+f"((c)[3]) \
                 : "r"(a0), "r"(a1), "r"(b0))

#define LDMX4(r0, r1, r2, r3, addr) \
    asm volatile("ldmatrix.sync.aligned.m8n8.x4.shared.b16 {%0,%1,%2,%3}, [%4];" \
                 : "=r"(r0), "=r"(r1), "=r"(r2), "=r"(r3) : "r"(addr))
#define LDMX2(r0, r1, addr) \
    asm volatile("ldmatrix.sync.aligned.m8n8.x2.shared.b16 {%0,%1}, [%2];" \
                 : "=r"(r0), "=r"(r1) : "r"(addr))
#define LDMX4T(r0, r1, r2, r3, addr) \
    asm volatile("ldmatrix.sync.aligned.m8n8.x4.trans.shared.b16 {%0,%1,%2,%3}, [%4];" \
                 : "=r"(r0), "=r"(r1), "=r"(r2), "=r"(r3) : "r"(addr))
#define LDMX2T(r0, r1, addr) \
    asm volatile("ldmatrix.sync.aligned.m8n8.x2.trans.shared.b16 {%0,%1}, [%2];" \
                 : "=r"(r0), "=r"(r1) : "r"(addr))

__device__ __forceinline__ void cp_async16(uint32_t s, const void* g) {
    asm volatile("cp.async.cg.shared.global [%0], [%1], 16;" :: "r"(s), "l"(g));
}
__device__ __forceinline__ void cp_commit() {
    asm volatile("cp.async.commit_group;");
}
template<int W> __device__ __forceinline__ void cp_wait() {
    asm volatile("cp.async.wait_group %0;" :: "n"(W));
}
__device__ __forceinline__ uint32_t smem_u32(const void* p) {
    return (uint32_t)__cvta_generic_to_shared(p);
}
__device__ __forceinline__ uint32_t h2u(__half2 h) {
    return *reinterpret_cast<uint32_t*>(&h);
}

// ---------------- weight transpose + fp32->half (batched) ----------------
struct TDesc { const float* src; __half* dst; int K; int N; };
struct TArgs { TDesc d[12]; };

__global__ void transpose_all_kernel(TArgs a)
{
    TDesc t = a.d[blockIdx.z];
    __shared__ float tile[32][33];
    int tx = threadIdx.x, ty = threadIdx.y;
    int x = blockIdx.x * 32 + tx;
    int y0 = blockIdx.y * 32;
    if (blockIdx.x * 32 >= t.N || y0 >= t.K) return;
    #pragma unroll
    for (int j = 0; j < 4; j++) {
        int y = y0 + ty + j * 8;
        if (y < t.K && x < t.N)
            tile[ty + j * 8][tx] = t.src[(size_t)y * t.N + x];
    }
    __syncthreads();
    int x2 = blockIdx.y * 32 + tx;
    int y20 = blockIdx.x * 32;
    #pragma unroll
    for (int j = 0; j < 4; j++) {
        int y2 = y20 + ty + j * 8;
        if (y2 < t.N && x2 < t.K)
            t.dst[(size_t)y2 * t.K + x2] = __float2half(tile[tx][ty + j * 8]);
    }
}

// ---------------- GroupNorm + transpose to [s,c], half out ----------------
__global__ void groupnorm_kernel(const float* __restrict__ x,
                                 const float* __restrict__ scale,
                                 const float* __restrict__ bias,
                                 __half* __restrict__ outT)
{
    const int g = blockIdx.x;
    const int c0 = g * 10;
    const int N = 10 * S_TOK;
    __shared__ float ssum[1024], ssq[1024];
    float s = 0.f, sq = 0.f;
    for (int i = threadIdx.x; i < N; i += 1024) {
        float v = x[c0 * S_TOK + i];
        s += v; sq += v * v;
    }
    ssum[threadIdx.x] = s; ssq[threadIdx.x] = sq;
    __syncthreads();
    for (int off = 512; off > 0; off >>= 1) {
        if (threadIdx.x < off) {
            ssum[threadIdx.x] += ssum[threadIdx.x + off];
            ssq[threadIdx.x]  += ssq[threadIdx.x + off];
        }
        __syncthreads();
    }
    __shared__ float smean, srstd;
    if (threadIdx.x == 0) {
        float mean = ssum[0] / (float)N;
        float var  = ssq[0] / (float)N - mean * mean;
        smean = mean;
        srstd = rsqrtf(var + 1e-6f);
    }
    __syncthreads();
    float mean = smean, rstd = srstd;
    for (int i = threadIdx.x; i < N; i += 1024) {
        int c = c0 + i / S_TOK;
        int sp = i - (i / S_TOK) * S_TOK;
        float v = (x[c0 * S_TOK + i] - mean) * rstd * scale[c] + bias[c];
        outT[sp * D_INNER + c] = __float2half(v);
    }
}

// ---------------- LayerNorm: warp/row, float2 loads, half2 stores ----------
__global__ void layernorm_kernel(const float* __restrict__ in,
                                 const float* __restrict__ s,
                                 const float* __restrict__ b,
                                 __half* __restrict__ out)
{
    int row = blockIdx.x * 8 + (threadIdx.x >> 5);
    int lane = threadIdx.x & 31;
    const float2* xr = reinterpret_cast<const float2*>(in + row * D_INNER);
    float2 v[5];
    float sum = 0.f, sq = 0.f;
    #pragma unroll
    for (int i = 0; i < 5; i++) {
        v[i] = xr[lane + i * 32];
        sum += v[i].x + v[i].y;
        sq  += v[i].x * v[i].x + v[i].y * v[i].y;
    }
    #pragma unroll
    for (int off = 16; off > 0; off >>= 1) {
        sum += __shfl_xor_sync(0xffffffffu, sum, off);
        sq  += __shfl_xor_sync(0xffffffffu, sq,  off);
    }
    float mean = sum / (float)D_INNER;
    float var  = sq / (float)D_INNER - mean * mean;
    float rstd = rsqrtf(var + 1e-5f);
    __half2* orow = reinterpret_cast<__half2*>(out + row * D_INNER);
    #pragma unroll
    for (int i = 0; i < 5; i++) {
        int j = (lane + i * 32) * 2;
        float y0 = (v[i].x - mean) * rstd * s[j]     + b[j];
        float y1 = (v[i].y - mean) * rstd * s[j + 1] + b[j + 1];
        orow[lane + i * 32] = __floats2half2_rn(y0, y1);
    }
}

// ---------------- fp16 GEMM: 64x64x32, 128 thr, 3-stage cp.async, ldmatrix ---
// A [M][K] half row-major; BT [N][K] half
#define GBM 64
#define GBN 64
#define GBK 32
#define STG 2560                       // halves per stage (64*40)
#define GEMM_SMEM_BYTES (6 * STG * 2)

__device__ __forceinline__ void gemm_core(
    const __half* __restrict__ A, const __half* __restrict__ BT,
    const float* __restrict__ bias, const float* __restrict__ resid,
    float* __restrict__ C32, __half* __restrict__ C16,
    int M, int N, int K, int flags, int bm, int bn)
{
    extern __shared__ __half smh[];
    const int tid = threadIdx.x;
    const int warp = tid >> 5, lane = tid & 31;
    const int wm = (warp >> 1) * 32, wn = (warp & 1) * 32;
    const int gid = lane >> 2, tig = lane & 3;

    float c[2][4][4];
    #pragma unroll
    for (int i = 0; i < 2; i++)
        #pragma unroll
        for (int j = 0; j < 4; j++)
            #pragma unroll
            for (int t = 0; t < 4; t++) c[i][j][t] = 0.f;

    const int nk = K / GBK;
    const int lr = tid >> 2;            // 0..31
    const int lc = (tid & 3) * 8;       // 0,8,16,24 halves

    auto load_stage = [&](int s, int k0) {
        #pragma unroll
        for (int i = 0; i < 2; i++) {
            int r = lr + i * 32;
            cp_async16(smem_u32(&smh[s * STG + r * 40 + lc]),
                       A + (size_t)(bm + r) * K + k0 + lc);
        }
        #pragma unroll
        for (int i = 0; i < 2; i++) {
            int r = lr + i * 32;
            cp_async16(smem_u32(&smh[3 * STG + s * STG + r * 40 + lc]),
                       BT + (size_t)(bn + r) * K + k0 + lc);
        }
    };

    load_stage(0, 0); cp_commit();
    load_stage(1, GBK); cp_commit();

    const int a_row = wm + (lane & 15);
    const int koff  = (lane >> 4) * 8;

    for (int t = 0; t < nk; t++) {
        cp_wait<1>();
        __syncthreads();
        if (t + 2 < nk) load_stage((t + 2) % 3, (t + 2) * GBK);
        cp_commit();

        const int s = t % 3;
        __half* as = &smh[s * STG];
        __half* bs = &smh[3 * STG + s * STG];

        #pragma unroll
        for (int ks = 0; ks < 2; ks++) {
            uint32_t af[2][4], bf[4][2];
            #pragma unroll
            for (int mt = 0; mt < 2; mt++) {
                uint32_t addr = smem_u32(&as[(a_row + mt * 16) * 40 + ks * 16 + koff]);
                LDMX4(af[mt][0], af[mt][1], af[mt][2], af[mt][3], addr);
            }
            #pragma unroll
            for (int p = 0; p < 2; p++) {
                uint32_t r0, r1, r2, r3;
                uint32_t addr = smem_u32(&bs[(wn + p * 16 + (lane & 15)) * 40 + ks * 16 + koff]);
                LDMX4(r0, r1, r2, r3, addr);
                bf[2 * p][0]     = r0; bf[2 * p][1]     = r2;
                bf[2 * p + 1][0] = r1; bf[2 * p + 1][1] = r3;
            }
            #pragma unroll
            for (int mt = 0; mt < 2; mt++)
                #pragma unroll
                for (int nt = 0; nt < 4; nt++)
                    MMA_F16(c[mt][nt], af[mt], bf[nt]);
        }
        __syncthreads();
    }

    #pragma unroll
    for (int mt = 0; mt < 2; mt++) {
        int r0 = bm + wm + mt * 16 + gid;
        int r1 = r0 + 8;
        #pragma unroll
        for (int nt = 0; nt < 4; nt++) {
            int col = bn + wn + nt * 8 + tig * 2;
            float v00 = c[mt][nt][0], v01 = c[mt][nt][1];
            float v10 = c[mt][nt][2], v11 = c[mt][nt][3];
            if (bias) {
                float b0 = bias[col], b1 = bias[col + 1];
                v00 += b0; v01 += b1; v10 += b0; v11 += b1;
            }
            if (flags & 2) {           // half out (no resid)
                *reinterpret_cast<__half2*>(&C16[(size_t)r0 * N + col]) = __floats2half2_rn(v00, v01);
                *reinterpret_cast<__half2*>(&C16[(size_t)r1 * N + col]) = __floats2half2_rn(v10, v11);
            } else if (flags & 1) {    // transposed fp32 store
                if (resid) {
                    v00 += resid[(size_t)col * M + r0];
                    v01 += resid[(size_t)(col + 1) * M + r0];
                    v10 += resid[(size_t)col * M + r1];
                    v11 += resid[(size_t)(col + 1) * M + r1];
                }
                C32[(size_t)col * M + r0]       = v00;
                C32[(size_t)(col + 1) * M + r0] = v01;
                C32[(size_t)col * M + r1]       = v10;
                C32[(size_t)(col + 1) * M + r1] = v11;
            } else {                   // fp32 (+ optional half dual)
                if (resid) {
                    v00 += resid[(size_t)r0 * N + col];
                    v01 += resid[(size_t)r0 * N + col + 1];
                    v10 += resid[(size_t)r1 * N + col];
                    v11 += resid[(size_t)r1 * N + col + 1];
                }
                C32[(size_t)r0 * N + col]     = v00;
                C32[(size_t)r0 * N + col + 1] = v01;
                C32[(size_t)r1 * N + col]     = v10;
                C32[(size_t)r1 * N + col + 1] = v11;
                if (flags & 4) {
                    *reinterpret_cast<__half2*>(&C16[(size_t)r0 * N + col]) = __floats2half2_rn(v00, v01);
                    *reinterpret_cast<__half2*>(&C16[(size_t)r1 * N + col]) = __floats2half2_rn(v10, v11);
                }
            }
        }
    }
}

__global__ __launch_bounds__(128)
void gemm_f16_kernel(const __half* __restrict__ A, const __half* __restrict__ BT,
                     const float* __restrict__ bias, const float* __restrict__ resid,
                     float* __restrict__ C32, __half* __restrict__ C16,
                     int M, int N, int K, int flags)
{
    gemm_core(A, BT, bias, resid, C32, C16, M, N, K, flags,
              blockIdx.y * GBM, blockIdx.x * GBN);
}

__global__ __launch_bounds__(128)
void gemm_qkv_kernel(const __half* __restrict__ A,
                     const __half* __restrict__ B0, const __half* __restrict__ B1,
                     const __half* __restrict__ B2,
                     __half* __restrict__ C0, __half* __restrict__ C1,
                     __half* __restrict__ C2, int M, int N, int K)
{
    const __half* B = (blockIdx.z == 0) ? B0 : (blockIdx.z == 1) ? B1 : B2;
    __half* C       = (blockIdx.z == 0) ? C0 : (blockIdx.z == 1) ? C1 : C2;
    gemm_core(A, B, nullptr, nullptr, nullptr, C, M, N, K, 2,
              blockIdx.y * GBM, blockIdx.x * GBN);
}

// ---------------- fp32 SGEMM for ctx K/V (small M=77), half out -------------
#define BM 64
#define BN 64
#define BKK 16
__global__ __launch_bounds__(256)
void sgemm_ctx_kernel(const float* __restrict__ A,
                      const float* __restrict__ B0, const float* __restrict__ B1,
                      __half* __restrict__ C0, __half* __restrict__ C1,
                      int M, int N, int K)
{
    const float* B = (blockIdx.z == 0) ? B0 : B1;
    __half* C      = (blockIdx.z == 0) ? C0 : C1;
    __shared__ float As[BKK][BM];
    __shared__ float Bs[BKK][BN];
    const int bm = blockIdx.y * BM;
    const int bn = blockIdx.x * BN;
    const int tid = threadIdx.x;
    const int tx = tid & 15;
    const int ty = tid >> 4;
    const int arow = tid >> 2;
    const int acol = (tid & 3) * 4;
    const int brow = tid >> 4;
    const int bcol = (tid & 15) * 4;

    float acc[4][4];
    #pragma unroll
    for (int i = 0; i < 4; i++)
        #pragma unroll
        for (int j = 0; j < 4; j++) acc[i][j] = 0.f;

    for (int k0 = 0; k0 < K; k0 += BKK) {
        float4 av = make_float4(0.f, 0.f, 0.f, 0.f);
        if (bm + arow < M)
            av = *reinterpret_cast<const float4*>(A + (size_t)(bm + arow) * K + k0 + acol);
        As[acol + 0][arow] = av.x;
        As[acol + 1][arow] = av.y;
        As[acol + 2][arow] = av.z;
        As[acol + 3][arow] = av.w;
        float4 bv = *reinterpret_cast<const float4*>(B + (size_t)(k0 + brow) * N + bn + bcol);
        *reinterpret_cast<float4*>(&Bs[brow][bcol]) = bv;
        __syncthreads();
        #pragma unroll
        for (int kk = 0; kk < BKK; kk++) {
            float4 a4 = *reinterpret_cast<const float4*>(&As[kk][ty * 4]);
            float4 b4 = *reinterpret_cast<const float4*>(&Bs[kk][tx * 4]);
            float a[4] = {a4.x, a4.y, a4.z, a4.w};
            float b[4] = {b4.x, b4.y, b4.z, b4.w};
            #pragma unroll
            for (int i = 0; i < 4; i++)
                #pragma unroll
                for (int j = 0; j < 4; j++)
                    acc[i][j] += a[i] * b[j];
        }
        __syncthreads();
    }

    #pragma unroll
    for (int i = 0; i < 4; i++) {
        int m = bm + ty * 4 + i;
        if (m >= M) continue;
        #pragma unroll
        for (int j = 0; j < 4; j++)
            C[(size_t)m * N + bn + tx * 4 + j] = __float2half(acc[i][j]);
    }
}

// ---------------- self-attention: flash fp16 mma ----------------------------
// block = 128 queries x 1 head, 8 warps
// smem halves: Ks[2][64][56] | Vs[2][64][56] | Ps[8][16][72]
#define KS_STG 3584
#define VS_BASE 7168
#define PS_BASE 14336
#define ATTN_SMEM_BYTES ((14336 + 9216) * 2)

__global__ __launch_bounds__(256, 2)
void attn_self_f16_kernel(const __half* __restrict__ q, const __half* __restrict__ k,
                          const __half* __restrict__ v, __half* __restrict__ o)
{
    extern __shared__ __half smh[];

    const int h = blockIdx.y;
    const int q0 = blockIdx.x * 128;
    const int tid = threadIdx.x;
    const int warp = tid >> 5, lane = tid & 31;
    const int gid = lane >> 2, tig = lane & 3;

    // Q fragments from gmem (unscaled; scale applied to S in fp32)
    uint32_t qf16[2][4], qf8[2];
    {
        const __half* qp0 = q + (size_t)(q0 + warp * 16 + gid) * D_INNER + h * 40;
        const __half* qp1 = qp0 + 8 * D_INNER;
        #pragma unroll
        for (int s = 0; s < 2; s++) {
            qf16[s][0] = *reinterpret_cast<const uint32_t*>(qp0 + s * 16 + 2 * tig);
            qf16[s][1] = *reinterpret_cast<const uint32_t*>(qp1 + s * 16 + 2 * tig);
            qf16[s][2] = *reinterpret_cast<const uint32_t*>(qp0 + s * 16 + 8 + 2 * tig);
            qf16[s][3] = *reinterpret_cast<const uint32_t*>(qp1 + s * 16 + 8 + 2 * tig);
        }
        qf8[0] = *reinterpret_cast<const uint32_t*>(qp0 + 32 + 2 * tig);
        qf8[1] = *reinterpret_cast<const uint32_t*>(qp1 + 32 + 2 * tig);
    }

    float oacc[5][4];
    #pragma unroll
    for (int nt = 0; nt < 5; nt++)
        #pragma unroll
        for (int t = 0; t < 4; t++) oacc[nt][t] = 0.f;
    float m0 = -1e30f, m1 = -1e30f, l0 = 0.f, l1 = 0.f;

    // K/V tile loader: 64 rows x 40 halves = 5 16B-chunks/row, x2 tensors = 640
    auto load_tile = [&](int buf, int t0) {
        #pragma unroll
        for (int j = 0; j < 3; j++) {
            int i = tid + j * 256;
            if (i < 640) {
                int row = i / 5;
                int c8 = (i - row * 5) * 8;
                size_t gi = (size_t)(t0 + row) * D_INNER + h * 40 + c8;
                cp_async16(smem_u32(&smh[buf * KS_STG + row * 56 + c8]), k + gi);
                cp_async16(smem_u32(&smh[VS_BASE + buf * KS_STG + row * 56 + c8]), v + gi);
            }
        }
    };

    load_tile(0, 0); cp_commit();

    __half* Pw = &smh[PS_BASE + warp * 16 * 72];
    const uint32_t p_ld_base = smem_u32(&Pw[(lane & 15) * 72 + ((lane >> 4) << 3)]);

    const int NTILES = S_TOK / 64;
    for (int t = 0; t < NTILES; t++) {
        __syncthreads();
        if (t + 1 < NTILES) load_tile((t + 1) & 1, (t + 1) * 64);
        cp_commit();
        cp_wait<1>();
        __syncthreads();

        const __half* ks_ = &smh[(t & 1) * KS_STG];
        const __half* vs_ = &smh[VS_BASE + (t & 1) * KS_STG];

        // ---- S = Q @ K^T ----
        float sc[8][4];
        #pragma unroll
        for (int nt = 0; nt < 8; nt++)
            #pragma unroll
            for (int e = 0; e < 4; e++) sc[nt][e] = 0.f;

        const int krow16 = lane & 15;
        const int koff   = (lane >> 4) << 3;
        const int krow8  = (lane & 7) + ((lane >> 3) & 1) * 8;
        #pragma unroll
        for (int p = 0; p < 4; p++) {
            #pragma unroll
            for (int s = 0; s < 2; s++) {
                uint32_t r0, r1, r2, r3;
                uint32_t addr = smem_u32(&ks_[(p * 16 + krow16) * 56 + s * 16 + koff]);
                LDMX4(r0, r1, r2, r3, addr);
                uint32_t b0[2] = {r0, r2}, b1[2] = {r1, r3};
                MMA_F16(sc[2 * p],     qf16[s], b0);
                MMA_F16(sc[2 * p + 1], qf16[s], b1);
            }
            uint32_t r0, r1;
            uint32_t addr = smem_u32(&ks_[(p * 16 + krow8) * 56 + 32]);
            LDMX2(r0, r1, addr);
            MMA_F16_K8(sc[2 * p],     qf8[0], qf8[1], r0);
            MMA_F16_K8(sc[2 * p + 1], qf8[0], qf8[1], r1);
        }
        #pragma unroll
        for (int nt = 0; nt < 8; nt++)
            #pragma unroll
            for (int e = 0; e < 4; e++) sc[nt][e] *= ATT_SCALE;

        // ---- online softmax (register) ----
        float t0m = -1e30f, t1m = -1e30f;
        #pragma unroll
        for (int nt = 0; nt < 8; nt++) {
            t0m = fmaxf(t0m, fmaxf(sc[nt][0], sc[nt][1]));
            t1m = fmaxf(t1m, fmaxf(sc[nt][2], sc[nt][3]));
        }
        t0m = fmaxf(t0m, __shfl_xor_sync(0xffffffffu, t0m, 1));
        t0m = fmaxf(t0m, __shfl_xor_sync(0xffffffffu, t0m, 2));
        t1m = fmaxf(t1m, __shfl_xor_sync(0xffffffffu, t1m, 1));
        t1m = fmaxf(t1m, __shfl_xor_sync(0xffffffffu, t1m, 2));

        float mn0 = fmaxf(m0, t0m), mn1 = fmaxf(m1, t1m);
        float corr0 = __expf(m0 - mn0), corr1 = __expf(m1 - mn1);
        float sum0 = 0.f, sum1 = 0.f;
        #pragma unroll
        for (int nt = 0; nt < 8; nt++) {
            float p00 = __expf(sc[nt][0] - mn0);
            float p01 = __expf(sc[nt][1] - mn0);
            float p10 = __expf(sc[nt][2] - mn1);
            float p11 = __expf(sc[nt][3] - mn1);
            sum0 += p00 + p01;
            sum1 += p10 + p11;
            *reinterpret_cast<__half2*>(&Pw[gid * 72 + nt * 8 + 2 * tig])       = __floats2half2_rn(p00, p01);
            *reinterpret_cast<__half2*>(&Pw[(gid + 8) * 72 + nt * 8 + 2 * tig]) = __floats2half2_rn(p10, p11);
        }
        sum0 += __shfl_xor_sync(0xffffffffu, sum0, 1);
        sum0 += __shfl_xor_sync(0xffffffffu, sum0, 2);
        sum1 += __shfl_xor_sync(0xffffffffu, sum1, 1);
        sum1 += __shfl_xor_sync(0xffffffffu, sum1, 2);
        l0 = l0 * corr0 + sum0;
        l1 = l1 * corr1 + sum1;
        m0 = mn0; m1 = mn1;

        #pragma unroll
        for (int nt = 0; nt < 5; nt++) {
            oacc[nt][0] *= corr0; oacc[nt][1] *= corr0;
            oacc[nt][2] *= corr1; oacc[nt][3] *= corr1;
        }
        __syncwarp();

        // ---- O += P @ V ----
        #pragma unroll
        for (int ks = 0; ks < 4; ks++) {
            uint32_t af[4];
            LDMX4(af[0], af[1], af[2], af[3], p_ld_base + ks * 32);
            #pragma unroll
            for (int c0 = 0; c0 < 2; c0++) {
                uint32_t r0, r1, r2, r3;
                uint32_t addr = smem_u32(&vs_[(ks * 16 + krow16) * 56 + c0 * 16 + koff]);
                LDMX4T(r0, r1, r2, r3, addr);
                uint32_t b0[2] = {r0, r1}, b1[2] = {r2, r3};
                MMA_F16(oacc[c0 * 2],     af, b0);
                MMA_F16(oacc[c0 * 2 + 1], af, b1);
            }
            uint32_t r0, r1;
            uint32_t addr = smem_u32(&vs_[(ks * 16 + krow8) * 56 + 32]);
            LDMX2T(r0, r1, addr);
            uint32_t b4[2] = {r0, r1};
            MMA_F16(oacc[4], af, b4);
        }
    }

    float inv0 = 1.f / l0, inv1 = 1.f / l1;
    size_t base0 = (size_t)(q0 + warp * 16 + gid) * D_INNER + h * 40;
    size_t base1 = base0 + 8 * D_INNER;
    #pragma unroll
    for (int nt = 0; nt < 5; nt++) {
        int col = nt * 8 + tig * 2;
        *reinterpret_cast<__half2*>(&o[base0 + col]) = __floats2half2_rn(oacc[nt][0] * inv0, oacc[nt][1] * inv0);
        *reinterpret_cast<__half2*>(&o[base1 + col]) = __floats2half2_rn(oacc[nt][2] * inv1, oacc[nt][3] * inv1);
    }
}

// ---------------- cross-attention (77 keys; half in/out, fp32 math) ---------
__global__ __launch_bounds__(128)
void attn_cross_kernel(const __half* __restrict__ q, const __half* __restrict__ k2,
                       const __half* __restrict__ v2, __half* __restrict__ o)
{
    __shared__ float Ks[CTX_LEN * 40];
    __shared__ float Vs[CTX_LEN * 40];
    const int h  = blockIdx.y;
    const int q0 = blockIdx.x * 128;
    const int tid = threadIdx.x;

    for (int idx = tid; idx < CTX_LEN * 40; idx += 128) {
        int r = idx / 40;
        int d = idx - r * 40;
        Ks[idx] = __half2float(k2[r * D_INNER + h * 40 + d]);
        Vs[idx] = __half2float(v2[r * D_INNER + h * 40 + d]);
    }
    __syncthreads();

    float qr[40];
    #pragma unroll
    for (int d = 0; d < 40; d++)
        qr[d] = __half2float(q[(size_t)(q0 + tid) * D_INNER + h * 40 + d]) * ATT_SCALE;

    float m = -1e30f;
    for (int j = 0; j < CTX_LEN; j++) {
        float s = 0.f;
        #pragma unroll
        for (int d = 0; d < 40; d++) s += qr[d] * Ks[j * 40 + d];
        m = fmaxf(m, s);
    }
    float l = 0.f;
    float accv[40];
    #pragma unroll
    for (int d = 0; d < 40; d++) accv[d] = 0.f;
    for (int j = 0; j < CTX_LEN; j++) {
        float s = 0.f;
        #pragma unroll
        for (int d = 0; d < 40; d++) s += qr[d] * Ks[j * 40 + d];
        float p = __expf(s - m);
        l += p;
        #pragma unroll
        for (int d = 0; d < 40; d++) accv[d] += p * Vs[j * 40 + d];
    }
    float inv = 1.f / l;
    #pragma unroll
    for (int d = 0; d < 40; d++)
        o[(size_t)(q0 + tid) * D_INNER + h * 40 + d] = __float2half(accv[d] * inv);
}

// ---------------- GEGLU: fp32 in, half out ----------------------------------
__global__ void geglu_kernel(const float* __restrict__ y, __half* __restrict__ act)
{
    int i2 = (blockIdx.x * 256 + threadIdx.x) * 2;
    if (i2 >= S_TOK * FF_HALF) return;
    int mrow = i2 / FF_HALF;
    int j = i2 - mrow * FF_HALF;
    float2 a = *reinterpret_cast<const float2*>(y + (size_t)mrow * FF_IN + j);
    float2 g = *reinterpret_cast<const float2*>(y + (size_t)mrow * FF_IN + FF_HALF + j);
    float ge0 = 0.5f * g.x * (1.f + erff(g.x * 0.70710678118654752f));
    float ge1 = 0.5f * g.y * (1.f + erff(g.y * 0.70710678118654752f));
    *reinterpret_cast<__half2*>(&act[i2]) = __floats2half2_rn(a.x * ge0, a.y * ge1);
}

// ---------------- host ----------------
static inline void gemm16(const __half* A, const __half* BT, const float* bias,
                          const float* resid, float* C32, __half* C16,
                          int M, int N, int K, int flags)
{
    dim3 grid(N / GBN, M / GBM);
    gemm_f16_kernel<<<grid, 128, GEMM_SMEM_BYTES>>>(A, BT, bias, resid, C32, C16, M, N, K, flags);
}

extern "C" void kernel_launch(void* const* d_in, const int* in_sizes, int n_in,
                              void* d_out, int out_size)
{
    const float* x          = (const float*)d_in[0];
    const float* context    = (const float*)d_in[1];
    const float* gn_scale   = (const float*)d_in[2];
    const float* gn_bias    = (const float*)d_in[3];
    const float* w_proj_in  = (const float*)d_in[4];
    const float* b_proj_in  = (const float*)d_in[5];
    const float* ln1_s      = (const float*)d_in[6];
    const float* ln1_b      = (const float*)d_in[7];
    const float* wq1        = (const float*)d_in[8];
    const float* wk1        = (const float*)d_in[9];
    const float* wv1        = (const float*)d_in[10];
    const float* wo1        = (const float*)d_in[11];
    const float* bo1        = (const float*)d_in[12];
    const float* ln2_s      = (const float*)d_in[13];
    const float* ln2_b      = (const float*)d_in[14];
    const float* wq2        = (const float*)d_in[15];
    const float* wk2        = (const float*)d_in[16];
    const float* wv2        = (const float*)d_in[17];
    const float* wo2        = (const float*)d_in[18];
    const float* bo2        = (const float*)d_in[19];
    const float* ln3_s      = (const float*)d_in[20];
    const float* ln3_b      = (const float*)d_in[21];
    const float* w_ff1      = (const float*)d_in[22];
    const float* b_ff1      = (const float*)d_in[23];
    const float* w_ff2      = (const float*)d_in[24];
    const float* b_ff2      = (const float*)d_in[25];
    const float* w_proj_out = (const float*)d_in[26];
    const float* b_proj_out = (const float*)d_in[27];
    float* out = (float*)d_out;

    float *h, *ff;
    __half *hh, *gn, *hn, *q, *k, *v, *attn, *act, *k2, *v2, *wT;
    cudaGetSymbolAddress((void**)&h,    g_h);
    cudaGetSymbolAddress((void**)&ff,   g_ff);
    cudaGetSymbolAddress((void**)&hh,   g_hh);
    cudaGetSymbolAddress((void**)&gn,   g_gn);
    cudaGetSymbolAddress((void**)&hn,   g_hn);
    cudaGetSymbolAddress((void**)&q,    g_q);
    cudaGetSymbolAddress((void**)&k,    g_k);
    cudaGetSymbolAddress((void**)&v,    g_v);
    cudaGetSymbolAddress((void**)&attn, g_at);
    cudaGetSymbolAddress((void**)&act,  g_act);
    cudaGetSymbolAddress((void**)&k2,   g_k2);
    cudaGetSymbolAddress((void**)&v2,   g_v2);
    cudaGetSymbolAddress((void**)&wT,   g_wTh);

    cudaFuncSetAttribute(gemm_f16_kernel, cudaFuncAttributeMaxDynamicSharedMemorySize, GEMM_SMEM_BYTES);
    cudaFuncSetAttribute(gemm_qkv_kernel, cudaFuncAttributeMaxDynamicSharedMemorySize, GEMM_SMEM_BYTES);
    cudaFuncSetAttribute(attn_self_f16_kernel, cudaFuncAttributeMaxDynamicSharedMemorySize, ATTN_SMEM_BYTES);

    __half* t_proj_in  = wT + 0;
    __half* t_wq1      = wT + 102400;
    __half* t_wk1      = wT + 204800;
    __half* t_wv1      = wT + 307200;
    __half* t_wo1      = wT + 409600;
    __half* t_wq2      = wT + 512000;
    __half* t_wk2      = wT + 614400;
    __half* t_wv2      = wT + 860160;
    __half* t_wo2      = wT + 1105920;
    __half* t_ff1      = wT + 1208320;
    __half* t_ff2      = wT + 2027520;
    __half* t_proj_out = wT + 2437120;

    TArgs ta;
    ta.d[0]  = {w_proj_in,  t_proj_in,  320,  320};
    ta.d[1]  = {wq1,        t_wq1,      320,  320};
    ta.d[2]  = {wk1,        t_wk1,      320,  320};
    ta.d[3]  = {wv1,        t_wv1,      320,  320};
    ta.d[4]  = {wo1,        t_wo1,      320,  320};
    ta.d[5]  = {wq2,        t_wq2,      320,  320};
    ta.d[6]  = {wk2,        t_wk2,      768,  320};
    ta.d[7]  = {wv2,        t_wv2,      768,  320};
    ta.d[8]  = {wo2,        t_wo2,      320,  320};
    ta.d[9]  = {w_ff1,      t_ff1,      320,  2560};
    ta.d[10] = {w_ff2,      t_ff2,      1280, 320};
    ta.d[11] = {w_proj_out, t_proj_out, 320,  320};
    transpose_all_kernel<<<dim3(80, 40, 12), dim3(32, 8)>>>(ta);

    groupnorm_kernel<<<32, 1024>>>(x, gn_scale, gn_bias, gn);
    gemm16(gn, t_proj_in, b_proj_in, nullptr, h, nullptr, S_TOK, D_INNER, D_INNER, 0);

    // --- self attention ---
    layernorm_kernel<<<S_TOK / 8, 256>>>(h, ln1_s, ln1_b, hn);
    {
        dim3 grid(D_INNER / GBN, S_TOK / GBM, 3);
        gemm_qkv_kernel<<<grid, 128, GEMM_SMEM_BYTES>>>(hn, t_wq1, t_wk1, t_wv1,
                                                        q, k, v, S_TOK, D_INNER, D_INNER);
    }
    attn_self_f16_kernel<<<dim3(S_TOK / 128, HEADS), 256, ATTN_SMEM_BYTES>>>(q, k, v, attn);
    gemm16(attn, t_wo1, bo1, h, h, nullptr, S_TOK, D_INNER, D_INNER, 0);

    // --- cross attention ---
    layernorm_kernel<<<S_TOK / 8, 256>>>(h, ln2_s, ln2_b, hn);
    gemm16(hn, t_wq2, nullptr, nullptr, nullptr, q, S_TOK, D_INNER, D_INNER, 2);
    sgemm_ctx_kernel<<<dim3(D_INNER / BN, (CTX_LEN + BM - 1) / BM, 2), 256>>>(
        context, wk2, wv2, k2, v2, CTX_LEN, D_INNER, CTX_DIM);
    attn_cross_kernel<<<dim3(S_TOK / 128, HEADS), 128>>>(q, k2, v2, attn);
    gemm16(attn, t_wo2, bo2, h, h, nullptr, S_TOK, D_INNER, D_INNER, 0);

    // --- GEGLU feed forward ---
    layernorm_kernel<<<S_TOK / 8, 256>>>(h, ln3_s, ln3_b, hn);
    gemm16(hn, t_ff1, b_ff1, nullptr, ff, nullptr, S_TOK, FF_IN, D_INNER, 0);
    geglu_kernel<<<(S_TOK * FF_HALF / 2 + 255) / 256, 256>>>(ff, act);
    gemm16(act, t_ff2, b_ff2, h, h, hh, S_TOK, D_INNER, FF_HALF, 4);  // dual: h fp32 + hh half

    // --- proj_out (transposed fp32 store) + input residual ---
    gemm16(hh, t_proj_out, b_proj_out, x, out, nullptr, S_TOK, D_INNER, D_INNER, 1);
}

// round 7
// speedup vs baseline: 5.1392x; 1.2680x over previous
#include <cuda_runtime.h>
#include <cuda_fp16.h>
#include <math.h>
#include <stdint.h>

#define S_TOK   4096
#define D_INNER 320
#define HEADS   8
#define DHEAD   40
#define CTX_LEN 77
#define CTX_DIM 768
#define FF_IN   2560
#define FF_HALF 1280
#define ATT_SCALE 0.15811388300841897f

// ---------------- scratch ----------------
__device__ float  g_h  [S_TOK * D_INNER];          // fp32 residual stream
__device__ __half g_hh [S_TOK * D_INNER];          // half copy of h (for proj_out)
__device__ __half g_gn [S_TOK * D_INNER];
__device__ __half g_hn [S_TOK * D_INNER];
__device__ __half g_q  [S_TOK * D_INNER];
__device__ __half g_k  [S_TOK * D_INNER];
__device__ __half g_v  [S_TOK * D_INNER];
__device__ __half g_at [S_TOK * D_INNER];
__device__ __half g_act[S_TOK * FF_HALF];
__device__ __half g_k2 [CTX_LEN * D_INNER];
__device__ __half g_v2 [CTX_LEN * D_INNER];
__device__ __half g_wTh[2539520];                  // all weights half, [n][k]
__device__ float  g_gnp[512];                      // groupnorm partials [32][8][2]

#define MMA_F16(c, a, b) \
    asm volatile("mma.sync.aligned.m16n8k16.row.col.f32.f16.f16.f32 " \
                 "{%0,%1,%2,%3},{%4,%5,%6,%7},{%8,%9},{%0,%1,%2,%3};" \
                 : "+f"((c)[0]), "+f"((c)[1]), "+f"((c)[2]), "+f"((c)[3]) \
                 : "r"((a)[0]), "r"((a)[1]), "r"((a)[2]), "r"((a)[3]), \
                   "r"((b)[0]), "r"((b)[1]))

#define MMA_F16_K8(c, a0, a1, b0) \
    asm volatile("mma.sync.aligned.m16n8k8.row.col.f32.f16.f16.f32 " \
                 "{%0,%1,%2,%3},{%4,%5},{%6},{%0,%1,%2,%3};" \
                 : "+f"((c)[0]), "+f"((c)[1]), "+f"((c)[2]), "+f"((c)[3]) \
                 : "r"(a0), "r"(a1), "r"(b0))

#define LDMX4(r0, r1, r2, r3, addr) \
    asm volatile("ldmatrix.sync.aligned.m8n8.x4.shared.b16 {%0,%1,%2,%3}, [%4];" \
                 : "=r"(r0), "=r"(r1), "=r"(r2), "=r"(r3) : "r"(addr))
#define LDMX2(r0, r1, addr) \
    asm volatile("ldmatrix.sync.aligned.m8n8.x2.shared.b16 {%0,%1}, [%2];" \
                 : "=r"(r0), "=r"(r1) : "r"(addr))
#define LDMX4T(r0, r1, r2, r3, addr) \
    asm volatile("ldmatrix.sync.aligned.m8n8.x4.trans.shared.b16 {%0,%1,%2,%3}, [%4];" \
                 : "=r"(r0), "=r"(r1), "=r"(r2), "=r"(r3) : "r"(addr))
#define LDMX2T(r0, r1, addr) \
    asm volatile("ldmatrix.sync.aligned.m8n8.x2.trans.shared.b16 {%0,%1}, [%2];" \
                 : "=r"(r0), "=r"(r1) : "r"(addr))

__device__ __forceinline__ void cp_async16(uint32_t s, const void* g) {
    asm volatile("cp.async.cg.shared.global [%0], [%1], 16;" :: "r"(s), "l"(g));
}
__device__ __forceinline__ void cp_commit() {
    asm volatile("cp.async.commit_group;");
}
template<int W> __device__ __forceinline__ void cp_wait() {
    asm volatile("cp.async.wait_group %0;" :: "n"(W));
}
__device__ __forceinline__ uint32_t smem_u32(const void* p) {
    return (uint32_t)__cvta_generic_to_shared(p);
}

// ---------------- weight transpose + fp32->half (flat tile grid) -------------
struct TDesc { const float* src; __half* dst; int K; int N; };
struct TArgs { TDesc d[12]; int off[13]; };

__global__ void transpose_all_kernel(TArgs a)
{
    int b = blockIdx.x;
    int s = 0;
    #pragma unroll
    for (int i = 0; i < 12; i++)
        if (b >= a.off[i + 1]) s = i + 1;
    TDesc t = a.d[s];
    int local = b - a.off[s];
    int tilesx = (t.N + 31) >> 5;
    int bx = local % tilesx;
    int by = local / tilesx;

    __shared__ float tile[32][33];
    int tx = threadIdx.x, ty = threadIdx.y;
    int x = bx * 32 + tx;
    int y0 = by * 32;
    #pragma unroll
    for (int j = 0; j < 4; j++) {
        int y = y0 + ty + j * 8;
        if (y < t.K && x < t.N)
            tile[ty + j * 8][tx] = t.src[(size_t)y * t.N + x];
    }
    __syncthreads();
    int x2 = by * 32 + tx;
    int y20 = bx * 32;
    #pragma unroll
    for (int j = 0; j < 4; j++) {
        int y2 = y20 + ty + j * 8;
        if (y2 < t.N && x2 < t.K)
            t.dst[(size_t)y2 * t.K + x2] = __float2half(tile[tx][ty + j * 8]);
    }
}

// ---------------- GroupNorm split: partial sums + apply ----------------------
__global__ void gn_part_kernel(const float* __restrict__ x)
{
    const int g = blockIdx.x, b = blockIdx.y;    // 32 x 8
    const float4* p = reinterpret_cast<const float4*>(x + g * 10 * S_TOK + b * 5120);
    float s = 0.f, sq = 0.f;
    #pragma unroll
    for (int i = 0; i < 5; i++) {
        float4 v = p[threadIdx.x + i * 256];
        s  += v.x + v.y + v.z + v.w;
        sq += v.x * v.x + v.y * v.y + v.z * v.z + v.w * v.w;
    }
    __shared__ float ss[256], sk[256];
    ss[threadIdx.x] = s; sk[threadIdx.x] = sq;
    __syncthreads();
    for (int off = 128; off > 0; off >>= 1) {
        if (threadIdx.x < off) {
            ss[threadIdx.x] += ss[threadIdx.x + off];
            sk[threadIdx.x] += sk[threadIdx.x + off];
        }
        __syncthreads();
    }
    if (threadIdx.x == 0) {
        g_gnp[(g * 8 + b) * 2]     = ss[0];
        g_gnp[(g * 8 + b) * 2 + 1] = sk[0];
    }
}

__global__ void gn_apply_kernel(const float* __restrict__ x,
                                const float* __restrict__ scale,
                                const float* __restrict__ bias,
                                __half* __restrict__ outT)
{
    const int g = blockIdx.x, b = blockIdx.y;
    float s = 0.f, sq = 0.f;
    #pragma unroll
    for (int i = 0; i < 8; i++) {
        s  += g_gnp[(g * 8 + i) * 2];
        sq += g_gnp[(g * 8 + i) * 2 + 1];
    }
    const float mean = s / 40960.f;
    const float rstd = rsqrtf(sq / 40960.f - mean * mean + 1e-6f);
    const int base = g * 10 * S_TOK + b * 5120;
    const float4* p = reinterpret_cast<const float4*>(x + base);
    #pragma unroll
    for (int i = 0; i < 5; i++) {
        int ii = threadIdx.x + i * 256;
        float4 v = p[ii];
        int idx = base + ii * 4;
        int c = idx >> 12;                 // idx / 4096
        int sp = idx & 4095;
        float sc = scale[c], bi = bias[c];
        outT[(sp + 0) * D_INNER + c] = __float2half((v.x - mean) * rstd * sc + bi);
        outT[(sp + 1) * D_INNER + c] = __float2half((v.y - mean) * rstd * sc + bi);
        outT[(sp + 2) * D_INNER + c] = __float2half((v.z - mean) * rstd * sc + bi);
        outT[(sp + 3) * D_INNER + c] = __float2half((v.w - mean) * rstd * sc + bi);
    }
}

// ---------------- LayerNorm ----------------
__global__ void layernorm_kernel(const float* __restrict__ in,
                                 const float* __restrict__ s,
                                 const float* __restrict__ b,
                                 __half* __restrict__ out)
{
    int row = blockIdx.x * 8 + (threadIdx.x >> 5);
    int lane = threadIdx.x & 31;
    const float2* xr = reinterpret_cast<const float2*>(in + row * D_INNER);
    float2 v[5];
    float sum = 0.f, sq = 0.f;
    #pragma unroll
    for (int i = 0; i < 5; i++) {
        v[i] = xr[lane + i * 32];
        sum += v[i].x + v[i].y;
        sq  += v[i].x * v[i].x + v[i].y * v[i].y;
    }
    #pragma unroll
    for (int off = 16; off > 0; off >>= 1) {
        sum += __shfl_xor_sync(0xffffffffu, sum, off);
        sq  += __shfl_xor_sync(0xffffffffu, sq,  off);
    }
    float mean = sum / (float)D_INNER;
    float var  = sq / (float)D_INNER - mean * mean;
    float rstd = rsqrtf(var + 1e-5f);
    __half2* orow = reinterpret_cast<__half2*>(out + row * D_INNER);
    #pragma unroll
    for (int i = 0; i < 5; i++) {
        int j = (lane + i * 32) * 2;
        float y0 = (v[i].x - mean) * rstd * s[j]     + b[j];
        float y1 = (v[i].y - mean) * rstd * s[j + 1] + b[j + 1];
        orow[lane + i * 32] = __floats2half2_rn(y0, y1);
    }
}

// ---------------- fp16 GEMM: 64x64x32, single-sync 3-stage pipeline ----------
#define GBM 64
#define GBN 64
#define GBK 32
#define STG 2560                       // halves per stage (64*40)
#define GEMM_SMEM_BYTES (6 * STG * 2)

__device__ __forceinline__ void gemm_core(
    const __half* __restrict__ A, const __half* __restrict__ BT,
    const float* __restrict__ bias, const float* __restrict__ resid,
    float* __restrict__ C32, __half* __restrict__ C16,
    int M, int N, int K, int flags, int bm, int bn)
{
    extern __shared__ __half smh[];
    const int tid = threadIdx.x;
    const int warp = tid >> 5, lane = tid & 31;
    const int wm = (warp >> 1) * 32, wn = (warp & 1) * 32;
    const int gid = lane >> 2, tig = lane & 3;

    float c[2][4][4];
    #pragma unroll
    for (int i = 0; i < 2; i++)
        #pragma unroll
        for (int j = 0; j < 4; j++)
            #pragma unroll
            for (int t = 0; t < 4; t++) c[i][j][t] = 0.f;

    const int nk = K / GBK;
    const int lr = tid >> 2;
    const int lc = (tid & 3) * 8;

    auto load_stage = [&](int s, int k0) {
        #pragma unroll
        for (int i = 0; i < 2; i++) {
            int r = lr + i * 32;
            cp_async16(smem_u32(&smh[s * STG + r * 40 + lc]),
                       A + (size_t)(bm + r) * K + k0 + lc);
        }
        #pragma unroll
        for (int i = 0; i < 2; i++) {
            int r = lr + i * 32;
            cp_async16(smem_u32(&smh[3 * STG + s * STG + r * 40 + lc]),
                       BT + (size_t)(bn + r) * K + k0 + lc);
        }
    };

    load_stage(0, 0); cp_commit();
    load_stage(1, GBK); cp_commit();

    const int a_row = wm + (lane & 15);
    const int koff  = (lane >> 4) * 8;

    for (int t = 0; t < nk; t++) {
        cp_wait<1>();
        __syncthreads();                       // single sync per iter
        if (t + 2 < nk) load_stage((t + 2) % 3, (t + 2) * GBK);
        cp_commit();                           // always commit (count discipline)

        const int s = t % 3;
        __half* as = &smh[s * STG];
        __half* bs = &smh[3 * STG + s * STG];

        #pragma unroll
        for (int ks = 0; ks < 2; ks++) {
            uint32_t af[2][4], bf[4][2];
            #pragma unroll
            for (int mt = 0; mt < 2; mt++) {
                uint32_t addr = smem_u32(&as[(a_row + mt * 16) * 40 + ks * 16 + koff]);
                LDMX4(af[mt][0], af[mt][1], af[mt][2], af[mt][3], addr);
            }
            #pragma unroll
            for (int p = 0; p < 2; p++) {
                uint32_t r0, r1, r2, r3;
                uint32_t addr = smem_u32(&bs[(wn + p * 16 + (lane & 15)) * 40 + ks * 16 + koff]);
                LDMX4(r0, r1, r2, r3, addr);
                bf[2 * p][0]     = r0; bf[2 * p][1]     = r2;
                bf[2 * p + 1][0] = r1; bf[2 * p + 1][1] = r3;
            }
            #pragma unroll
            for (int mt = 0; mt < 2; mt++)
                #pragma unroll
                for (int nt = 0; nt < 4; nt++)
                    MMA_F16(c[mt][nt], af[mt], bf[nt]);
        }
    }

    #pragma unroll
    for (int mt = 0; mt < 2; mt++) {
        int r0 = bm + wm + mt * 16 + gid;
        int r1 = r0 + 8;
        #pragma unroll
        for (int nt = 0; nt < 4; nt++) {
            int col = bn + wn + nt * 8 + tig * 2;
            float v00 = c[mt][nt][0], v01 = c[mt][nt][1];
            float v10 = c[mt][nt][2], v11 = c[mt][nt][3];
            if (bias) {
                float b0 = bias[col], b1 = bias[col + 1];
                v00 += b0; v01 += b1; v10 += b0; v11 += b1;
            }
            if (flags & 2) {
                *reinterpret_cast<__half2*>(&C16[(size_t)r0 * N + col]) = __floats2half2_rn(v00, v01);
                *reinterpret_cast<__half2*>(&C16[(size_t)r1 * N + col]) = __floats2half2_rn(v10, v11);
            } else if (flags & 1) {
                if (resid) {
                    v00 += resid[(size_t)col * M + r0];
                    v01 += resid[(size_t)(col + 1) * M + r0];
                    v10 += resid[(size_t)col * M + r1];
                    v11 += resid[(size_t)(col + 1) * M + r1];
                }
                C32[(size_t)col * M + r0]       = v00;
                C32[(size_t)(col + 1) * M + r0] = v01;
                C32[(size_t)col * M + r1]       = v10;
                C32[(size_t)(col + 1) * M + r1] = v11;
            } else {
                if (resid) {
                    v00 += resid[(size_t)r0 * N + col];
                    v01 += resid[(size_t)r0 * N + col + 1];
                    v10 += resid[(size_t)r1 * N + col];
                    v11 += resid[(size_t)r1 * N + col + 1];
                }
                C32[(size_t)r0 * N + col]     = v00;
                C32[(size_t)r0 * N + col + 1] = v01;
                C32[(size_t)r1 * N + col]     = v10;
                C32[(size_t)r1 * N + col + 1] = v11;
                if (flags & 4) {
                    *reinterpret_cast<__half2*>(&C16[(size_t)r0 * N + col]) = __floats2half2_rn(v00, v01);
                    *reinterpret_cast<__half2*>(&C16[(size_t)r1 * N + col]) = __floats2half2_rn(v10, v11);
                }
            }
        }
    }
}

__global__ __launch_bounds__(128)
void gemm_f16_kernel(const __half* __restrict__ A, const __half* __restrict__ BT,
                     const float* __restrict__ bias, const float* __restrict__ resid,
                     float* __restrict__ C32, __half* __restrict__ C16,
                     int M, int N, int K, int flags)
{
    gemm_core(A, BT, bias, resid, C32, C16, M, N, K, flags,
              blockIdx.y * GBM, blockIdx.x * GBN);
}

__global__ __launch_bounds__(128)
void gemm_qkv_kernel(const __half* __restrict__ A,
                     const __half* __restrict__ B0, const __half* __restrict__ B1,
                     const __half* __restrict__ B2,
                     __half* __restrict__ C0, __half* __restrict__ C1,
                     __half* __restrict__ C2, int M, int N, int K)
{
    const __half* B = (blockIdx.z == 0) ? B0 : (blockIdx.z == 1) ? B1 : B2;
    __half* C       = (blockIdx.z == 0) ? C0 : (blockIdx.z == 1) ? C1 : C2;
    gemm_core(A, B, nullptr, nullptr, nullptr, C, M, N, K, 2,
              blockIdx.y * GBM, blockIdx.x * GBN);
}

// ---------------- fused ff1 + GEGLU: act = (hn@Wa+ba) * gelu(hn@Wg+bg) -------
// A [M][320] half; BT [2560][320] half; act [M][1280] half
#define FF1_SMEM_BYTES (9 * STG * 2)   // 3 stages x (A + Ba + Bg)
__global__ __launch_bounds__(128)
void gemm_ff1g_kernel(const __half* __restrict__ A, const __half* __restrict__ BT,
                      const float* __restrict__ bias, __half* __restrict__ act,
                      int M, int K)
{
    extern __shared__ __half smh[];
    const int bm = blockIdx.y * GBM;
    const int bn = blockIdx.x * GBN;
    const int tid = threadIdx.x;
    const int warp = tid >> 5, lane = tid & 31;
    const int wm = (warp >> 1) * 32, wn = (warp & 1) * 32;
    const int gid = lane >> 2, tig = lane & 3;

    float ca[2][4][4], cg[2][4][4];
    #pragma unroll
    for (int i = 0; i < 2; i++)
        #pragma unroll
        for (int j = 0; j < 4; j++)
            #pragma unroll
            for (int t = 0; t < 4; t++) { ca[i][j][t] = 0.f; cg[i][j][t] = 0.f; }

    const int nk = K / GBK;    // 10
    const int lr = tid >> 2;
    const int lc = (tid & 3) * 8;

    auto load_stage = [&](int s, int k0) {
        #pragma unroll
        for (int i = 0; i < 2; i++) {
            int r = lr + i * 32;
            cp_async16(smem_u32(&smh[s * STG + r * 40 + lc]),
                       A + (size_t)(bm + r) * K + k0 + lc);
            cp_async16(smem_u32(&smh[3 * STG + s * STG + r * 40 + lc]),
                       BT + (size_t)(bn + r) * K + k0 + lc);
            cp_async16(smem_u32(&smh[6 * STG + s * STG + r * 40 + lc]),
                       BT + (size_t)(FF_HALF + bn + r) * K + k0 + lc);
        }
    };

    load_stage(0, 0); cp_commit();
    load_stage(1, GBK); cp_commit();

    const int a_row = wm + (lane & 15);
    const int koff  = (lane >> 4) * 8;

    for (int t = 0; t < nk; t++) {
        cp_wait<1>();
        __syncthreads();
        if (t + 2 < nk) load_stage((t + 2) % 3, (t + 2) * GBK);
        cp_commit();

        const int s = t % 3;
        __half* as  = &smh[s * STG];
        __half* bsa = &smh[3 * STG + s * STG];
        __half* bsg = &smh[6 * STG + s * STG];

        #pragma unroll
        for (int ks = 0; ks < 2; ks++) {
            uint32_t af[2][4], bfa[4][2], bfg[4][2];
            #pragma unroll
            for (int mt = 0; mt < 2; mt++) {
                uint32_t addr = smem_u32(&as[(a_row + mt * 16) * 40 + ks * 16 + koff]);
                LDMX4(af[mt][0], af[mt][1], af[mt][2], af[mt][3], addr);
            }
            #pragma unroll
            for (int p = 0; p < 2; p++) {
                uint32_t r0, r1, r2, r3;
                uint32_t addr = smem_u32(&bsa[(wn + p * 16 + (lane & 15)) * 40 + ks * 16 + koff]);
                LDMX4(r0, r1, r2, r3, addr);
                bfa[2 * p][0] = r0; bfa[2 * p][1] = r2;
                bfa[2 * p + 1][0] = r1; bfa[2 * p + 1][1] = r3;
                addr = smem_u32(&bsg[(wn + p * 16 + (lane & 15)) * 40 + ks * 16 + koff]);
                LDMX4(r0, r1, r2, r3, addr);
                bfg[2 * p][0] = r0; bfg[2 * p][1] = r2;
                bfg[2 * p + 1][0] = r1; bfg[2 * p + 1][1] = r3;
            }
            #pragma unroll
            for (int mt = 0; mt < 2; mt++)
                #pragma unroll
                for (int nt = 0; nt < 4; nt++) {
                    MMA_F16(ca[mt][nt], af[mt], bfa[nt]);
                    MMA_F16(cg[mt][nt], af[mt], bfg[nt]);
                }
        }
    }

    #pragma unroll
    for (int mt = 0; mt < 2; mt++) {
        int r0 = bm + wm + mt * 16 + gid;
        int r1 = r0 + 8;
        #pragma unroll
        for (int nt = 0; nt < 4; nt++) {
            int col = bn + wn + nt * 8 + tig * 2;
            float ba0 = bias[col], ba1 = bias[col + 1];
            float bg0 = bias[FF_HALF + col], bg1 = bias[FF_HALF + col + 1];
            float a00 = ca[mt][nt][0] + ba0, a01 = ca[mt][nt][1] + ba1;
            float a10 = ca[mt][nt][2] + ba0, a11 = ca[mt][nt][3] + ba1;
            float g00 = cg[mt][nt][0] + bg0, g01 = cg[mt][nt][1] + bg1;
            float g10 = cg[mt][nt][2] + bg0, g11 = cg[mt][nt][3] + bg1;
            const float inv_s2 = 0.70710678118654752f;
            float e00 = 0.5f * g00 * (1.f + erff(g00 * inv_s2));
            float e01 = 0.5f * g01 * (1.f + erff(g01 * inv_s2));
            float e10 = 0.5f * g10 * (1.f + erff(g10 * inv_s2));
            float e11 = 0.5f * g11 * (1.f + erff(g11 * inv_s2));
            *reinterpret_cast<__half2*>(&act[(size_t)r0 * FF_HALF + col]) =
                __floats2half2_rn(a00 * e00, a01 * e01);
            *reinterpret_cast<__half2*>(&act[(size_t)r1 * FF_HALF + col]) =
                __floats2half2_rn(a10 * e10, a11 * e11);
        }
    }
}

// ---------------- fp32 SGEMM for ctx K/V (small M=77), half out -------------
#define BM 64
#define BN 64
#define BKK 16
__global__ __launch_bounds__(256)
void sgemm_ctx_kernel(const float* __restrict__ A,
                      const float* __restrict__ B0, const float* __restrict__ B1,
                      __half* __restrict__ C0, __half* __restrict__ C1,
                      int M, int N, int K)
{
    const float* B = (blockIdx.z == 0) ? B0 : B1;
    __half* C      = (blockIdx.z == 0) ? C0 : C1;
    __shared__ float As[BKK][BM];
    __shared__ float Bs[BKK][BN];
    const int bm = blockIdx.y * BM;
    const int bn = blockIdx.x * BN;
    const int tid = threadIdx.x;
    const int tx = tid & 15;
    const int ty = tid >> 4;
    const int arow = tid >> 2;
    const int acol = (tid & 3) * 4;
    const int brow = tid >> 4;
    const int bcol = (tid & 15) * 4;

    float acc[4][4];
    #pragma unroll
    for (int i = 0; i < 4; i++)
        #pragma unroll
        for (int j = 0; j < 4; j++) acc[i][j] = 0.f;

    for (int k0 = 0; k0 < K; k0 += BKK) {
        float4 av = make_float4(0.f, 0.f, 0.f, 0.f);
        if (bm + arow < M)
            av = *reinterpret_cast<const float4*>(A + (size_t)(bm + arow) * K + k0 + acol);
        As[acol + 0][arow] = av.x;
        As[acol + 1][arow] = av.y;
        As[acol + 2][arow] = av.z;
        As[acol + 3][arow] = av.w;
        float4 bv = *reinterpret_cast<const float4*>(B + (size_t)(k0 + brow) * N + bn + bcol);
        *reinterpret_cast<float4*>(&Bs[brow][bcol]) = bv;
        __syncthreads();
        #pragma unroll
        for (int kk = 0; kk < BKK; kk++) {
            float4 a4 = *reinterpret_cast<const float4*>(&As[kk][ty * 4]);
            float4 b4 = *reinterpret_cast<const float4*>(&Bs[kk][tx * 4]);
            float a[4] = {a4.x, a4.y, a4.z, a4.w};
            float b[4] = {b4.x, b4.y, b4.z, b4.w};
            #pragma unroll
            for (int i = 0; i < 4; i++)
                #pragma unroll
                for (int j = 0; j < 4; j++)
                    acc[i][j] += a[i] * b[j];
        }
        __syncthreads();
    }

    #pragma unroll
    for (int i = 0; i < 4; i++) {
        int m = bm + ty * 4 + i;
        if (m >= M) continue;
        #pragma unroll
        for (int j = 0; j < 4; j++)
            C[(size_t)m * N + bn + tx * 4 + j] = __float2half(acc[i][j]);
    }
}

// ---------------- self-attention: flash fp16 mma, single-sync pipeline -------
#define KS_STG 3584
#define VS_BASE 7168
#define PS_BASE 14336
#define ATTN_SMEM_BYTES ((14336 + 9216) * 2)

__global__ __launch_bounds__(256, 2)
void attn_self_f16_kernel(const __half* __restrict__ q, const __half* __restrict__ k,
                          const __half* __restrict__ v, __half* __restrict__ o)
{
    extern __shared__ __half smh[];

    const int h = blockIdx.y;
    const int q0 = blockIdx.x * 128;
    const int tid = threadIdx.x;
    const int warp = tid >> 5, lane = tid & 31;
    const int gid = lane >> 2, tig = lane & 3;

    uint32_t qf16[2][4], qf8[2];
    {
        const __half* qp0 = q + (size_t)(q0 + warp * 16 + gid) * D_INNER + h * 40;
        const __half* qp1 = qp0 + 8 * D_INNER;
        #pragma unroll
        for (int s = 0; s < 2; s++) {
            qf16[s][0] = *reinterpret_cast<const uint32_t*>(qp0 + s * 16 + 2 * tig);
            qf16[s][1] = *reinterpret_cast<const uint32_t*>(qp1 + s * 16 + 2 * tig);
            qf16[s][2] = *reinterpret_cast<const uint32_t*>(qp0 + s * 16 + 8 + 2 * tig);
            qf16[s][3] = *reinterpret_cast<const uint32_t*>(qp1 + s * 16 + 8 + 2 * tig);
        }
        qf8[0] = *reinterpret_cast<const uint32_t*>(qp0 + 32 + 2 * tig);
        qf8[1] = *reinterpret_cast<const uint32_t*>(qp1 + 32 + 2 * tig);
    }

    float oacc[5][4];
    #pragma unroll
    for (int nt = 0; nt < 5; nt++)
        #pragma unroll
        for (int t = 0; t < 4; t++) oacc[nt][t] = 0.f;
    float m0 = -1e30f, m1 = -1e30f, l0 = 0.f, l1 = 0.f;

    auto load_tile = [&](int buf, int t0) {
        #pragma unroll
        for (int j = 0; j < 3; j++) {
            int i = tid + j * 256;
            if (i < 640) {
                int row = i / 5;
                int c8 = (i - row * 5) * 8;
                size_t gi = (size_t)(t0 + row) * D_INNER + h * 40 + c8;
                cp_async16(smem_u32(&smh[buf * KS_STG + row * 56 + c8]), k + gi);
                cp_async16(smem_u32(&smh[VS_BASE + buf * KS_STG + row * 56 + c8]), v + gi);
            }
        }
    };

    load_tile(0, 0); cp_commit();

    __half* Pw = &smh[PS_BASE + warp * 16 * 72];
    const uint32_t p_ld_base = smem_u32(&Pw[(lane & 15) * 72 + ((lane >> 4) << 3)]);

    const int NTILES = S_TOK / 64;
    for (int t = 0; t < NTILES; t++) {
        cp_wait<0>();
        __syncthreads();                 // single block sync per tile
        if (t + 1 < NTILES) load_tile((t + 1) & 1, (t + 1) * 64);
        cp_commit();

        const __half* ks_ = &smh[(t & 1) * KS_STG];
        const __half* vs_ = &smh[VS_BASE + (t & 1) * KS_STG];

        // ---- S = Q @ K^T ----
        float sc[8][4];
        #pragma unroll
        for (int nt = 0; nt < 8; nt++)
            #pragma unroll
            for (int e = 0; e < 4; e++) sc[nt][e] = 0.f;

        const int krow16 = lane & 15;
        const int koff   = (lane >> 4) << 3;
        const int krow8  = (lane & 7) + ((lane >> 3) & 1) * 8;
        #pragma unroll
        for (int p = 0; p < 4; p++) {
            #pragma unroll
            for (int s = 0; s < 2; s++) {
                uint32_t r0, r1, r2, r3;
                uint32_t addr = smem_u32(&ks_[(p * 16 + krow16) * 56 + s * 16 + koff]);
                LDMX4(r0, r1, r2, r3, addr);
                uint32_t b0[2] = {r0, r2}, b1[2] = {r1, r3};
                MMA_F16(sc[2 * p],     qf16[s], b0);
                MMA_F16(sc[2 * p + 1], qf16[s], b1);
            }
            uint32_t r0, r1;
            uint32_t addr = smem_u32(&ks_[(p * 16 + krow8) * 56 + 32]);
            LDMX2(r0, r1, addr);
            MMA_F16_K8(sc[2 * p],     qf8[0], qf8[1], r0);
            MMA_F16_K8(sc[2 * p + 1], qf8[0], qf8[1], r1);
        }
        #pragma unroll
        for (int nt = 0; nt < 8; nt++)
            #pragma unroll
            for (int e = 0; e < 4; e++) sc[nt][e] *= ATT_SCALE;

        // ---- online softmax (register) ----
        float t0m = -1e30f, t1m = -1e30f;
        #pragma unroll
        for (int nt = 0; nt < 8; nt++) {
            t0m = fmaxf(t0m, fmaxf(sc[nt][0], sc[nt][1]));
            t1m = fmaxf(t1m, fmaxf(sc[nt][2], sc[nt][3]));
        }
        t0m = fmaxf(t0m, __shfl_xor_sync(0xffffffffu, t0m, 1));
        t0m = fmaxf(t0m, __shfl_xor_sync(0xffffffffu, t0m, 2));
        t1m = fmaxf(t1m, __shfl_xor_sync(0xffffffffu, t1m, 1));
        t1m = fmaxf(t1m, __shfl_xor_sync(0xffffffffu, t1m, 2));

        float mn0 = fmaxf(m0, t0m), mn1 = fmaxf(m1, t1m);
        float corr0 = __expf(m0 - mn0), corr1 = __expf(m1 - mn1);
        float sum0 = 0.f, sum1 = 0.f;
        #pragma unroll
        for (int nt = 0; nt < 8; nt++) {
            float p00 = __expf(sc[nt][0] - mn0);
            float p01 = __expf(sc[nt][1] - mn0);
            float p10 = __expf(sc[nt][2] - mn1);
            float p11 = __expf(sc[nt][3] - mn1);
            sum0 += p00 + p01;
            sum1 += p10 + p11;
            *reinterpret_cast<__half2*>(&Pw[gid * 72 + nt * 8 + 2 * tig])       = __floats2half2_rn(p00, p01);
            *reinterpret_cast<__half2*>(&Pw[(gid + 8) * 72 + nt * 8 + 2 * tig]) = __floats2half2_rn(p10, p11);
        }
        sum0 += __shfl_xor_sync(0xffffffffu, sum0, 1);
        sum0 += __shfl_xor_sync(0xffffffffu, sum0, 2);
        sum1 += __shfl_xor_sync(0xffffffffu, sum1, 1);
        sum1 += __shfl_xor_sync(0xffffffffu, sum1, 2);
        l0 = l0 * corr0 + sum0;
        l1 = l1 * corr1 + sum1;
        m0 = mn0; m1 = mn1;

        #pragma unroll
        for (int nt = 0; nt < 5; nt++) {
            oacc[nt][0] *= corr0; oacc[nt][1] *= corr0;
            oacc[nt][2] *= corr1; oacc[nt][3] *= corr1;
        }
        __syncwarp();

        // ---- O += P @ V ----
        #pragma unroll
        for (int ks = 0; ks < 4; ks++) {
            uint32_t af[4];
            LDMX4(af[0], af[1], af[2], af[3], p_ld_base + ks * 32);
            #pragma unroll
            for (int c0 = 0; c0 < 2; c0++) {
                uint32_t r0, r1, r2, r3;
                uint32_t addr = smem_u32(&vs_[(ks * 16 + krow16) * 56 + c0 * 16 + koff]);
                LDMX4T(r0, r1, r2, r3, addr);
                uint32_t b0[2] = {r0, r1}, b1[2] = {r2, r3};
                MMA_F16(oacc[c0 * 2],     af, b0);
                MMA_F16(oacc[c0 * 2 + 1], af, b1);
            }
            uint32_t r0, r1;
            uint32_t addr = smem_u32(&vs_[(ks * 16 + krow8) * 56 + 32]);
            LDMX2T(r0, r1, addr);
            uint32_t b4[2] = {r0, r1};
            MMA_F16(oacc[4], af, b4);
        }
    }

    float inv0 = 1.f / l0, inv1 = 1.f / l1;
    size_t base0 = (size_t)(q0 + warp * 16 + gid) * D_INNER + h * 40;
    size_t base1 = base0 + 8 * D_INNER;
    #pragma unroll
    for (int nt = 0; nt < 5; nt++) {
        int col = nt * 8 + tig * 2;
        *reinterpret_cast<__half2*>(&o[base0 + col]) = __floats2half2_rn(oacc[nt][0] * inv0, oacc[nt][1] * inv0);
        *reinterpret_cast<__half2*>(&o[base1 + col]) = __floats2half2_rn(oacc[nt][2] * inv1, oacc[nt][3] * inv1);
    }
}

// ---------------- cross-attention (77 keys; half in/out, fp32 math) ---------
__global__ __launch_bounds__(128)
void attn_cross_kernel(const __half* __restrict__ q, const __half* __restrict__ k2,
                       const __half* __restrict__ v2, __half* __restrict__ o)
{
    __shared__ float Ks[CTX_LEN * 40];
    __shared__ float Vs[CTX_LEN * 40];
    const int h  = blockIdx.y;
    const int q0 = blockIdx.x * 128;
    const int tid = threadIdx.x;

    for (int idx = tid; idx < CTX_LEN * 40; idx += 128) {
        int r = idx / 40;
        int d = idx - r * 40;
        Ks[idx] = __half2float(k2[r * D_INNER + h * 40 + d]);
        Vs[idx] = __half2float(v2[r * D_INNER + h * 40 + d]);
    }
    __syncthreads();

    float qr[40];
    #pragma unroll
    for (int d = 0; d < 40; d++)
        qr[d] = __half2float(q[(size_t)(q0 + tid) * D_INNER + h * 40 + d]) * ATT_SCALE;

    float m = -1e30f;
    for (int j = 0; j < CTX_LEN; j++) {
        float s = 0.f;
        #pragma unroll
        for (int d = 0; d < 40; d++) s += qr[d] * Ks[j * 40 + d];
        m = fmaxf(m, s);
    }
    float l = 0.f;
    float accv[40];
    #pragma unroll
    for (int d = 0; d < 40; d++) accv[d] = 0.f;
    for (int j = 0; j < CTX_LEN; j++) {
        float s = 0.f;
        #pragma unroll
        for (int d = 0; d < 40; d++) s += qr[d] * Ks[j * 40 + d];
        float p = __expf(s - m);
        l += p;
        #pragma unroll
        for (int d = 0; d < 40; d++) accv[d] += p * Vs[j * 40 + d];
    }
    float inv = 1.f / l;
    #pragma unroll
    for (int d = 0; d < 40; d++)
        o[(size_t)(q0 + tid) * D_INNER + h * 40 + d] = __float2half(accv[d] * inv);
}

// ---------------- host ----------------
static inline void gemm16(const __half* A, const __half* BT, const float* bias,
                          const float* resid, float* C32, __half* C16,
                          int M, int N, int K, int flags)
{
    dim3 grid(N / GBN, M / GBM);
    gemm_f16_kernel<<<grid, 128, GEMM_SMEM_BYTES>>>(A, BT, bias, resid, C32, C16, M, N, K, flags);
}

extern "C" void kernel_launch(void* const* d_in, const int* in_sizes, int n_in,
                              void* d_out, int out_size)
{
    const float* x          = (const float*)d_in[0];
    const float* context    = (const float*)d_in[1];
    const float* gn_scale   = (const float*)d_in[2];
    const float* gn_bias    = (const float*)d_in[3];
    const float* w_proj_in  = (const float*)d_in[4];
    const float* b_proj_in  = (const float*)d_in[5];
    const float* ln1_s      = (const float*)d_in[6];
    const float* ln1_b      = (const float*)d_in[7];
    const float* wq1        = (const float*)d_in[8];
    const float* wk1        = (const float*)d_in[9];
    const float* wv1        = (const float*)d_in[10];
    const float* wo1        = (const float*)d_in[11];
    const float* bo1        = (const float*)d_in[12];
    const float* ln2_s      = (const float*)d_in[13];
    const float* ln2_b      = (const float*)d_in[14];
    const float* wq2        = (const float*)d_in[15];
    const float* wk2        = (const float*)d_in[16];
    const float* wv2        = (const float*)d_in[17];
    const float* wo2        = (const float*)d_in[18];
    const float* bo2        = (const float*)d_in[19];
    const float* ln3_s      = (const float*)d_in[20];
    const float* ln3_b      = (const float*)d_in[21];
    const float* w_ff1      = (const float*)d_in[22];
    const float* b_ff1      = (const float*)d_in[23];
    const float* w_ff2      = (const float*)d_in[24];
    const float* b_ff2      = (const float*)d_in[25];
    const float* w_proj_out = (const float*)d_in[26];
    const float* b_proj_out = (const float*)d_in[27];
    float* out = (float*)d_out;

    float *h;
    __half *hh, *gn, *hn, *q, *k, *v, *attn, *act, *k2, *v2, *wT;
    cudaGetSymbolAddress((void**)&h,    g_h);
    cudaGetSymbolAddress((void**)&hh,   g_hh);
    cudaGetSymbolAddress((void**)&gn,   g_gn);
    cudaGetSymbolAddress((void**)&hn,   g_hn);
    cudaGetSymbolAddress((void**)&q,    g_q);
    cudaGetSymbolAddress((void**)&k,    g_k);
    cudaGetSymbolAddress((void**)&v,    g_v);
    cudaGetSymbolAddress((void**)&attn, g_at);
    cudaGetSymbolAddress((void**)&act,  g_act);
    cudaGetSymbolAddress((void**)&k2,   g_k2);
    cudaGetSymbolAddress((void**)&v2,   g_v2);
    cudaGetSymbolAddress((void**)&wT,   g_wTh);

    cudaFuncSetAttribute(gemm_f16_kernel, cudaFuncAttributeMaxDynamicSharedMemorySize, GEMM_SMEM_BYTES);
    cudaFuncSetAttribute(gemm_qkv_kernel, cudaFuncAttributeMaxDynamicSharedMemorySize, GEMM_SMEM_BYTES);
    cudaFuncSetAttribute(gemm_ff1g_kernel, cudaFuncAttributeMaxDynamicSharedMemorySize, FF1_SMEM_BYTES);
    cudaFuncSetAttribute(attn_self_f16_kernel, cudaFuncAttributeMaxDynamicSharedMemorySize, ATTN_SMEM_BYTES);

    __half* t_proj_in  = wT + 0;
    __half* t_wq1      = wT + 102400;
    __half* t_wk1      = wT + 204800;
    __half* t_wv1      = wT + 307200;
    __half* t_wo1      = wT + 409600;
    __half* t_wq2      = wT + 512000;
    __half* t_wk2      = wT + 614400;
    __half* t_wv2      = wT + 860160;
    __half* t_wo2      = wT + 1105920;
    __half* t_ff1      = wT + 1208320;
    __half* t_ff2      = wT + 2027520;
    __half* t_proj_out = wT + 2437120;

    TArgs ta;
    ta.d[0]  = {w_proj_in,  t_proj_in,  320,  320};
    ta.d[1]  = {wq1,        t_wq1,      320,  320};
    ta.d[2]  = {wk1,        t_wk1,      320,  320};
    ta.d[3]  = {wv1,        t_wv1,      320,  320};
    ta.d[4]  = {wo1,        t_wo1,      320,  320};
    ta.d[5]  = {wq2,        t_wq2,      320,  320};
    ta.d[6]  = {wk2,        t_wk2,      768,  320};
    ta.d[7]  = {wv2,        t_wv2,      768,  320};
    ta.d[8]  = {wo2,        t_wo2,      320,  320};
    ta.d[9]  = {w_ff1,      t_ff1,      320,  2560};
    ta.d[10] = {w_ff2,      t_ff2,      1280, 320};
    ta.d[11] = {w_proj_out, t_proj_out, 320,  320};
    ta.off[0] = 0;
    for (int s = 0; s < 12; s++) {
        int tx = (ta.d[s].N + 31) / 32;
        int ty = (ta.d[s].K + 31) / 32;
        ta.off[s + 1] = ta.off[s] + tx * ty;
    }
    transpose_all_kernel<<<ta.off[12], dim3(32, 8)>>>(ta);

    gn_part_kernel<<<dim3(32, 8), 256>>>(x);
    gn_apply_kernel<<<dim3(32, 8), 256>>>(x, gn_scale, gn_bias, gn);
    gemm16(gn, t_proj_in, b_proj_in, nullptr, h, nullptr, S_TOK, D_INNER, D_INNER, 0);

    // --- self attention ---
    layernorm_kernel<<<S_TOK / 8, 256>>>(h, ln1_s, ln1_b, hn);
    {
        dim3 grid(D_INNER / GBN, S_TOK / GBM, 3);
        gemm_qkv_kernel<<<grid, 128, GEMM_SMEM_BYTES>>>(hn, t_wq1, t_wk1, t_wv1,
                                                        q, k, v, S_TOK, D_INNER, D_INNER);
    }
    attn_self_f16_kernel<<<dim3(S_TOK / 128, HEADS), 256, ATTN_SMEM_BYTES>>>(q, k, v, attn);
    gemm16(attn, t_wo1, bo1, h, h, nullptr, S_TOK, D_INNER, D_INNER, 0);

    // --- cross attention ---
    layernorm_kernel<<<S_TOK / 8, 256>>>(h, ln2_s, ln2_b, hn);
    gemm16(hn, t_wq2, nullptr, nullptr, nullptr, q, S_TOK, D_INNER, D_INNER, 2);
    sgemm_ctx_kernel<<<dim3(D_INNER / BN, (CTX_LEN + BM - 1) / BM, 2), 256>>>(
        context, wk2, wv2, k2, v2, CTX_LEN, D_INNER, CTX_DIM);
    attn_cross_kernel<<<dim3(S_TOK / 128, HEADS), 128>>>(q, k2, v2, attn);
    gemm16(attn, t_wo2, bo2, h, h, nullptr, S_TOK, D_INNER, D_INNER, 0);

    // --- fused GEGLU feed forward ---
    layernorm_kernel<<<S_TOK / 8, 256>>>(h, ln3_s, ln3_b, hn);
    {
        dim3 grid(FF_HALF / GBN, S_TOK / GBM);
        gemm_ff1g_kernel<<<grid, 128, FF1_SMEM_BYTES>>>(hn, t_ff1, b_ff1, act,
                                                        S_TOK, D_INNER);
    }
    gemm16(act, t_ff2, b_ff2, h, h, hh, S_TOK, D_INNER, FF_HALF, 4);

    // --- proj_out (transposed fp32 store) + input residual ---
    gemm16(hh, t_proj_out, b_proj_out, x, out, nullptr, S_TOK, D_INNER, D_INNER, 1);
}